// round 8
// baseline (speedup 1.0000x reference)
#include <cuda_runtime.h>
#include <math.h>
#include <stdint.h>

#define N_NODES  20000
#define N_EDGES  320000
#define NUM_G    64
#define D1       256
#define D2       128
#define BSTRIDE  96      // bucket slots per node; Poisson(16) => P(deg>=96) ~ 0

// ---------------- scratch (device globals) -------------
__device__ float g_dinv[N_NODES];
__device__ int   g_cnt[N_NODES];
__device__ int   g_cursor[N_NODES];
__device__ int   g_bucket[(size_t)N_NODES * BSTRIDE];
__device__ uint4 g_h1b[(size_t)N_NODES * (D1 / 8)];  // bf16x2-packed dinv*(x@W1)
__device__ float g_a1[(size_t)N_NODES * D1];         // relu(Ahat h1 + b1), fp32
__device__ uint2 g_h2b[(size_t)N_NODES * (D2 / 4)];  // bf16x2-packed dinv*(a1@W2)
__device__ float g_pool[NUM_G * D2];
__device__ float g_pcnt[NUM_G];

// ---------------- helpers ----------------
__device__ __forceinline__ uint32_t f2tf32(float f) {
    uint32_t u;
    asm("cvt.rna.tf32.f32 %0, %1;" : "=r"(u) : "f"(f));
    return u;
}
__device__ __forceinline__ uint32_t f2bf2(float lo, float hi) {
    uint32_t r;
    asm("cvt.rn.bf16x2.f32 %0, %1, %2;" : "=r"(r) : "f"(hi), "f"(lo));
    return r;
}
__device__ __forceinline__ void addbf2(float* a, uint32_t u) {
    a[0] += __uint_as_float(u << 16);
    a[1] += __uint_as_float(u & 0xffff0000u);
}

// ---------------- init ----------------
__global__ void k_init() {
    int i = blockIdx.x * blockDim.x + threadIdx.x;
    if (i < N_NODES) { g_cnt[i] = 0; g_cursor[i] = 0; }
    if (i < NUM_G * D2) g_pool[i] = 0.0f;
    if (i < NUM_G) g_pcnt[i] = 0.0f;
}

// ---------------- degree histogram over dst (x4 vectorized) ----------------
__global__ void k_cnt(const int* __restrict__ ei) {
    int t = blockIdx.x * blockDim.x + threadIdx.x;
    if (t < N_EDGES / 4) {
        int4 d = ((const int4*)(ei + N_EDGES))[t];
        atomicAdd(&g_cnt[d.x], 1);
        atomicAdd(&g_cnt[d.y], 1);
        atomicAdd(&g_cnt[d.z], 1);
        atomicAdd(&g_cnt[d.w], 1);
    }
}

__global__ void k_dinv() {
    int i = blockIdx.x * blockDim.x + threadIdx.x;
    if (i < N_NODES) g_dinv[i] = rsqrtf((float)(g_cnt[i] + 1));  // +1 self loop
}

// ---------------- bucket fill (no scan needed) ----------------
__global__ void k_fill(const int* __restrict__ ei) {
    int e = blockIdx.x * blockDim.x + threadIdx.x;
    if (e < N_EDGES) {
        int d = ei[N_EDGES + e];
        int pos = atomicAdd(&g_cursor[d], 1);
        if (pos < BSTRIDE) g_bucket[(size_t)d * BSTRIDE + pos] = ei[e];
    }
}

// ---------------- tf32 tensor-core GEMM; epilogue: *dinv, pack bf16x2 -------
__device__ __forceinline__ void mma8(float* acc, const uint32_t* a, const uint32_t* b) {
    asm volatile(
        "mma.sync.aligned.m16n8k8.row.col.f32.tf32.tf32.f32 "
        "{%0,%1,%2,%3},{%4,%5,%6,%7},{%8,%9},{%0,%1,%2,%3};"
        : "+f"(acc[0]), "+f"(acc[1]), "+f"(acc[2]), "+f"(acc[3])
        : "r"(a[0]), "r"(a[1]), "r"(a[2]), "r"(a[3]), "r"(b[0]), "r"(b[1]));
}

// C_bf16[M,N] = dinv[row] * (A[M,256] @ B[256,N]). BM=128, BN=64, BK=32.
template<int LAYER>
__global__ __launch_bounds__(256) void gemm_tc(const float* __restrict__ Ain,
                                               const float* __restrict__ Bw) {
    constexpr int K = 256;
    constexpr int N = (LAYER == 0) ? 256 : 128;
    constexpr int M = N_NODES;
    const float* A = (LAYER == 0) ? Ain : (const float*)g_a1;
    uint32_t* C = (LAYER == 0) ? (uint32_t*)g_h1b : (uint32_t*)g_h2b;

    __shared__ uint32_t As[128 * 36];
    __shared__ uint32_t Bs[32 * 72];

    int tid = threadIdx.x, lane = tid & 31, warp = tid >> 5;
    int wm = warp & 3, wn = warp >> 2;
    int row0 = blockIdx.x * 128, col0 = blockIdx.y * 64;

    int am = tid >> 1, ah = (tid & 1) * 16;
    int bk = tid >> 4, bn = (tid & 15) * 4;

    float acc[2][4][4];
    #pragma unroll
    for (int mt = 0; mt < 2; mt++)
        #pragma unroll
        for (int nt = 0; nt < 4; nt++)
            #pragma unroll
            for (int i = 0; i < 4; i++) acc[mt][nt][i] = 0.0f;

    float4 areg[4];
    float4 breg[2];
    bool aok = (row0 + am) < M;
    const float* aptr = A + (size_t)(row0 + am) * K + ah;
    const float* bptr = Bw + (size_t)bk * N + col0 + bn;

    auto ldg = [&](int k0) {
        #pragma unroll
        for (int j = 0; j < 4; j++)
            areg[j] = aok ? *(const float4*)(aptr + k0 + 4 * j)
                          : make_float4(0.f, 0.f, 0.f, 0.f);
        breg[0] = *(const float4*)(bptr + (size_t)k0 * N);
        breg[1] = *(const float4*)(bptr + (size_t)(k0 + 16) * N);
    };
    auto sts = [&]() {
        #pragma unroll
        for (int j = 0; j < 4; j++) {
            uint4 u = make_uint4(f2tf32(areg[j].x), f2tf32(areg[j].y),
                                 f2tf32(areg[j].z), f2tf32(areg[j].w));
            *(uint4*)&As[am * 36 + ah + 4 * j] = u;
        }
        uint4 u0 = make_uint4(f2tf32(breg[0].x), f2tf32(breg[0].y),
                              f2tf32(breg[0].z), f2tf32(breg[0].w));
        uint4 u1 = make_uint4(f2tf32(breg[1].x), f2tf32(breg[1].y),
                              f2tf32(breg[1].z), f2tf32(breg[1].w));
        *(uint4*)&Bs[bk * 72 + bn] = u0;
        *(uint4*)&Bs[(bk + 16) * 72 + bn] = u1;
    };
    int r = lane >> 2, c = lane & 3;
    auto compute = [&]() {
        #pragma unroll
        for (int kk = 0; kk < 32; kk += 8) {
            uint32_t af[2][4], bf[4][2];
            #pragma unroll
            for (int mt = 0; mt < 2; mt++) {
                int m0 = wm * 32 + mt * 16 + r;
                af[mt][0] = As[m0 * 36 + kk + c];
                af[mt][1] = As[(m0 + 8) * 36 + kk + c];
                af[mt][2] = As[m0 * 36 + kk + c + 4];
                af[mt][3] = As[(m0 + 8) * 36 + kk + c + 4];
            }
            #pragma unroll
            for (int nt = 0; nt < 4; nt++) {
                int n0 = wn * 32 + nt * 8 + r;
                bf[nt][0] = Bs[(kk + c) * 72 + n0];
                bf[nt][1] = Bs[(kk + c + 4) * 72 + n0];
            }
            #pragma unroll
            for (int mt = 0; mt < 2; mt++)
                #pragma unroll
                for (int nt = 0; nt < 4; nt++)
                    mma8(acc[mt][nt], af[mt], bf[nt]);
        }
    };

    ldg(0);
    sts();
    __syncthreads();
    for (int t = 1; t < 8; t++) {
        ldg(t * 32);
        compute();
        __syncthreads();
        sts();
        __syncthreads();
    }
    compute();

    constexpr int NU = N / 2;  // uint32 per row
    #pragma unroll
    for (int mt = 0; mt < 2; mt++) {
        int gr = row0 + wm * 32 + mt * 16 + r;
        bool ok0 = gr < M, ok1 = (gr + 8) < M;
        float dv0 = ok0 ? g_dinv[gr] : 0.0f;
        float dv1 = ok1 ? g_dinv[gr + 8] : 0.0f;
        #pragma unroll
        for (int nt = 0; nt < 4; nt++) {
            int gcu = (col0 + wn * 32 + nt * 8) / 2 + c;
            if (ok0)
                C[(size_t)gr * NU + gcu] =
                    f2bf2(acc[mt][nt][0] * dv0, acc[mt][nt][1] * dv0);
            if (ok1)
                C[(size_t)(gr + 8) * NU + gcu] =
                    f2bf2(acc[mt][nt][2] * dv1, acc[mt][nt][3] * dv1);
        }
    }
}

// ---------------- aggregation over bf16-packed h, bucket adjacency ----------
// out[v] = relu(dinv[v] * (h[v] + sum_{s in N(v)} h[s]) + b)
template<int LAYER>
__global__ void agg_kernel(const float* __restrict__ bias,
                           const int* __restrict__ batch) {
    constexpr int NA = (LAYER == 0) ? 8 : 4;   // floats per lane
    int w    = (blockIdx.x * blockDim.x + threadIdx.x) >> 5;
    int lane = threadIdx.x & 31;
    if (w >= N_NODES) return;
    float dv = g_dinv[w];
    float acc[NA];
    #pragma unroll
    for (int j = 0; j < NA; j++) acc[j] = 0.0f;
    int deg = min(g_cnt[w], BSTRIDE);
    const int* bk = g_bucket + (size_t)w * BSTRIDE;

    if (LAYER == 0) {
        const uint4* h = (const uint4*)g_h1b;
        uint4 u = h[(size_t)w * 32 + lane];      // self term
        addbf2(acc + 0, u.x); addbf2(acc + 2, u.y);
        addbf2(acc + 4, u.z); addbf2(acc + 6, u.w);
        int e = 0;
        for (; e + 4 <= deg; e += 4) {
            int s0 = bk[e], s1 = bk[e + 1], s2 = bk[e + 2], s3 = bk[e + 3];
            uint4 u0 = h[(size_t)s0 * 32 + lane];
            uint4 u1 = h[(size_t)s1 * 32 + lane];
            uint4 u2 = h[(size_t)s2 * 32 + lane];
            uint4 u3 = h[(size_t)s3 * 32 + lane];
            addbf2(acc + 0, u0.x); addbf2(acc + 2, u0.y);
            addbf2(acc + 4, u0.z); addbf2(acc + 6, u0.w);
            addbf2(acc + 0, u1.x); addbf2(acc + 2, u1.y);
            addbf2(acc + 4, u1.z); addbf2(acc + 6, u1.w);
            addbf2(acc + 0, u2.x); addbf2(acc + 2, u2.y);
            addbf2(acc + 4, u2.z); addbf2(acc + 6, u2.w);
            addbf2(acc + 0, u3.x); addbf2(acc + 2, u3.y);
            addbf2(acc + 4, u3.z); addbf2(acc + 6, u3.w);
        }
        for (; e < deg; e++) {
            uint4 uu = h[(size_t)bk[e] * 32 + lane];
            addbf2(acc + 0, uu.x); addbf2(acc + 2, uu.y);
            addbf2(acc + 4, uu.z); addbf2(acc + 6, uu.w);
        }
        float o[8];
        #pragma unroll
        for (int j = 0; j < 8; j++)
            o[j] = fmaxf(dv * acc[j] + bias[lane * 8 + j], 0.0f);
        float4* dst = (float4*)(g_a1 + (size_t)w * D1 + lane * 8);
        dst[0] = make_float4(o[0], o[1], o[2], o[3]);
        dst[1] = make_float4(o[4], o[5], o[6], o[7]);
    } else {
        const uint2* h = (const uint2*)g_h2b;
        uint2 u = h[(size_t)w * 32 + lane];
        addbf2(acc + 0, u.x); addbf2(acc + 2, u.y);
        int e = 0;
        for (; e + 4 <= deg; e += 4) {
            int s0 = bk[e], s1 = bk[e + 1], s2 = bk[e + 2], s3 = bk[e + 3];
            uint2 u0 = h[(size_t)s0 * 32 + lane];
            uint2 u1 = h[(size_t)s1 * 32 + lane];
            uint2 u2 = h[(size_t)s2 * 32 + lane];
            uint2 u3 = h[(size_t)s3 * 32 + lane];
            addbf2(acc + 0, u0.x); addbf2(acc + 2, u0.y);
            addbf2(acc + 0, u1.x); addbf2(acc + 2, u1.y);
            addbf2(acc + 0, u2.x); addbf2(acc + 2, u2.y);
            addbf2(acc + 0, u3.x); addbf2(acc + 2, u3.y);
        }
        for (; e < deg; e++) {
            uint2 uu = h[(size_t)bk[e] * 32 + lane];
            addbf2(acc + 0, uu.x); addbf2(acc + 2, uu.y);
        }
        int g = batch[w];
        #pragma unroll
        for (int j = 0; j < 4; j++) {
            float v = fmaxf(dv * acc[j] + bias[lane * 4 + j], 0.0f);
            atomicAdd(&g_pool[g * D2 + lane * 4 + j], v);
        }
        if (lane == 0) atomicAdd(&g_pcnt[g], 1.0f);
    }
}

// ---------------- MLP head ----------------
__global__ void k_head(const float* __restrict__ Wl1, const float* __restrict__ bl1,
                       const float* __restrict__ Wl2, const float* __restrict__ bl2,
                       float* __restrict__ out) {
    __shared__ float gv[128];
    __shared__ float hid[64];
    int g = blockIdx.x, t = threadIdx.x;
    float cgt = fmaxf(g_pcnt[g], 1.0f);
    gv[t] = g_pool[g * D2 + t] / cgt;
    __syncthreads();
    if (t < 64) {
        float s = bl1[t];
        #pragma unroll 4
        for (int k = 0; k < 128; k++) s += gv[k] * Wl1[k * 64 + t];
        hid[t] = fmaxf(s, 0.0f);
    }
    __syncthreads();
    if (t == 0) {
        float s = bl2[0];
        #pragma unroll 4
        for (int k = 0; k < 64; k++) s += hid[k] * Wl2[k];
        out[g] = 1.0f / (1.0f + expf(-s));
    }
}

// ---------------- launch ----------------
extern "C" void kernel_launch(void* const* d_in, const int* in_sizes, int n_in,
                              void* d_out, int out_size) {
    const float* x    = (const float*)d_in[0];
    const int*   ei   = (const int*)d_in[1];
    const int*   bat  = (const int*)d_in[2];
    const float* W1   = (const float*)d_in[3];
    const float* b1   = (const float*)d_in[4];
    const float* W2   = (const float*)d_in[5];
    const float* b2   = (const float*)d_in[6];
    const float* Wl1  = (const float*)d_in[7];
    const float* bl1  = (const float*)d_in[8];
    const float* Wl2  = (const float*)d_in[9];
    const float* bl2  = (const float*)d_in[10];
    float* out = (float*)d_out;

    cudaStream_t s1;
    cudaEvent_t evA, evDinv, evCsr;
    cudaStreamCreateWithFlags(&s1, cudaStreamNonBlocking);
    cudaEventCreateWithFlags(&evA,    cudaEventDisableTiming);
    cudaEventCreateWithFlags(&evDinv, cudaEventDisableTiming);
    cudaEventCreateWithFlags(&evCsr,  cudaEventDisableTiming);

    cudaEventRecord(evA, 0);
    cudaStreamWaitEvent(s1, evA, 0);

    // side branch: degree count -> dinv -> bucket fill (no scan)
    k_init<<<(N_NODES + 255) / 256, 256, 0, s1>>>();
    k_cnt<<<(N_EDGES / 4 + 255) / 256, 256, 0, s1>>>(ei);
    k_dinv<<<(N_NODES + 255) / 256, 256, 0, s1>>>();
    cudaEventRecord(evDinv, s1);
    k_fill<<<(N_EDGES + 255) / 256, 256, 0, s1>>>(ei);
    cudaEventRecord(evCsr, s1);

    // main branch
    cudaStreamWaitEvent(0, evDinv, 0);
    {
        dim3 grid((N_NODES + 127) / 128, D1 / 64);
        gemm_tc<0><<<grid, 256>>>(x, W1);
    }
    cudaStreamWaitEvent(0, evCsr, 0);
    agg_kernel<0><<<(N_NODES * 32 + 255) / 256, 256>>>(b1, nullptr);

    {
        dim3 grid((N_NODES + 127) / 128, D2 / 64);
        gemm_tc<1><<<grid, 256>>>(nullptr, W2);
    }
    agg_kernel<1><<<(N_NODES * 32 + 255) / 256, 256>>>(b2, bat);

    k_head<<<NUM_G, 128>>>(Wl1, bl1, Wl2, bl2, out);
}

// round 9
// speedup vs baseline: 1.1492x; 1.1492x over previous
#include <cuda_runtime.h>
#include <math.h>
#include <stdint.h>

#define N_NODES  20000
#define N_EDGES  320000
#define NUM_G    64
#define D1       256
#define D2       128
#define BSTRIDE  96      // bucket slots per node; Poisson(16) => P(deg>=96) ~ 0

// ---------------- scratch (device globals) -------------
__device__ float g_dinv[N_NODES];
__device__ int   g_cnt[N_NODES];
__device__ int   g_cursor[N_NODES];
__device__ int   g_bucket[(size_t)N_NODES * BSTRIDE];
__device__ uint4 g_h1b[(size_t)N_NODES * (D1 / 8)];  // bf16x2-packed dinv*(x@W1)
__device__ uint4 g_a1b[(size_t)N_NODES * (D1 / 8)];  // bf16x2-packed relu(...)
__device__ uint2 g_h2b[(size_t)N_NODES * (D2 / 4)];  // bf16x2-packed dinv*(a1@W2)
__device__ float g_pool[NUM_G * D2];
__device__ float g_pcnt[NUM_G];

// ---------------- helpers ----------------
__device__ __forceinline__ uint32_t f2bf2(float lo, float hi) {
    uint32_t r;
    asm("cvt.rn.bf16x2.f32 %0, %1, %2;" : "=r"(r) : "f"(hi), "f"(lo));
    return r;
}
__device__ __forceinline__ void addbf2(float* a, uint32_t u) {
    a[0] += __uint_as_float(u << 16);
    a[1] += __uint_as_float(u & 0xffff0000u);
}

// ---------------- init ----------------
__global__ void k_init() {
    int i = blockIdx.x * blockDim.x + threadIdx.x;
    if (i < N_NODES) { g_cnt[i] = 0; g_cursor[i] = 0; }
    if (i < NUM_G * D2) g_pool[i] = 0.0f;
    if (i < NUM_G) g_pcnt[i] = 0.0f;
}

// ---------------- degree histogram over dst ----------------
__global__ void k_cnt(const int* __restrict__ ei) {
    int t = blockIdx.x * blockDim.x + threadIdx.x;
    if (t < N_EDGES / 4) {
        int4 d = ((const int4*)(ei + N_EDGES))[t];
        atomicAdd(&g_cnt[d.x], 1);
        atomicAdd(&g_cnt[d.y], 1);
        atomicAdd(&g_cnt[d.z], 1);
        atomicAdd(&g_cnt[d.w], 1);
    }
}

__global__ void k_dinv() {
    int i = blockIdx.x * blockDim.x + threadIdx.x;
    if (i < N_NODES) g_dinv[i] = rsqrtf((float)(g_cnt[i] + 1));  // +1 self loop
}

// ---------------- bucket fill ----------------
__global__ void k_fill(const int* __restrict__ ei) {
    int e = blockIdx.x * blockDim.x + threadIdx.x;
    if (e < N_EDGES) {
        int d = ei[N_EDGES + e];
        int pos = atomicAdd(&g_cursor[d], 1);
        if (pos < BSTRIDE) g_bucket[(size_t)d * BSTRIDE + pos] = ei[e];
    }
}

// ---------------- bf16 tensor-core GEMM (m16n8k16) ----------------
__device__ __forceinline__ void mma16(float* d, const uint32_t* a, const uint32_t* b) {
    asm volatile(
        "mma.sync.aligned.m16n8k16.row.col.f32.bf16.bf16.f32 "
        "{%0,%1,%2,%3},{%4,%5,%6,%7},{%8,%9},{%0,%1,%2,%3};"
        : "+f"(d[0]), "+f"(d[1]), "+f"(d[2]), "+f"(d[3])
        : "r"(a[0]), "r"(a[1]), "r"(a[2]), "r"(a[3]), "r"(b[0]), "r"(b[1]));
}

// C_bf16[M,N] = dinv[row] * (A[M,256] @ B[256,N]). BM=128, BN=128, BK=32.
// 256 threads = 8 warps (4 x 2), warp tile 32x64.
// LAYER 0: A = x (fp32, converted on the fly). LAYER 1: A = g_a1b (bf16 packed).
template<int LAYER>
__global__ __launch_bounds__(256, 2) void gemm_bf(const float* __restrict__ Ain,
                                                  const float* __restrict__ Bw) {
    constexpr int K = 256;
    constexpr int N = (LAYER == 0) ? 256 : 128;
    constexpr int M = N_NODES;
    uint32_t* C = (LAYER == 0) ? (uint32_t*)g_h1b : (uint32_t*)g_h2b;

    __shared__ uint32_t As[128 * 20];   // [m][kpair], kpair 0..15, stride 20
    __shared__ uint32_t Bs[16 * 132];   // [kpair][n],  n 0..127,  stride 132

    int tid = threadIdx.x, lane = tid & 31, warp = tid >> 5;
    int wm = warp & 3, wn = warp >> 2;            // 4 x 2
    int row0 = blockIdx.x * 128, col0 = blockIdx.y * 128;

    int am = tid >> 1, ahp = (tid & 1) * 8;       // A: row am, kpair offset ahp
    int bkp = tid >> 4, bn = (tid & 15) * 8;      // B: kpair row bkp, cols bn..bn+7

    float acc[2][8][4];
    #pragma unroll
    for (int mt = 0; mt < 2; mt++)
        #pragma unroll
        for (int nt = 0; nt < 8; nt++)
            #pragma unroll
            for (int i = 0; i < 4; i++) acc[mt][nt][i] = 0.0f;

    bool aok = (row0 + am) < M;
    float4 areg[4];            // layer0 staging (16 fp32)
    uint4  areg1[2];           // layer1 staging (16 bf16)
    float4 breg[4];            // B staging: rows 2bkp, 2bkp+1, 8 cols

    const float* aptr0 = Ain + (size_t)(row0 + am) * K + ahp * 2;
    const uint4* aptr1 = g_a1b + (size_t)(row0 + am) * 32 + (tid & 1) * 2;
    const float* bptr = Bw + (size_t)(2 * bkp) * N + col0 + bn;

    auto ldg = [&](int k0) {
        if (LAYER == 0) {
            #pragma unroll
            for (int j = 0; j < 4; j++)
                areg[j] = aok ? *(const float4*)(aptr0 + k0 + 4 * j)
                              : make_float4(0.f, 0.f, 0.f, 0.f);
        } else {
            #pragma unroll
            for (int j = 0; j < 2; j++)
                areg1[j] = aok ? aptr1[k0 / 8 + j]
                               : make_uint4(0u, 0u, 0u, 0u);
        }
        const float* bp = bptr + (size_t)k0 * N;
        breg[0] = *(const float4*)(bp);
        breg[1] = *(const float4*)(bp + 4);
        breg[2] = *(const float4*)(bp + N);
        breg[3] = *(const float4*)(bp + N + 4);
    };
    auto sts = [&]() {
        if (LAYER == 0) {
            uint4 u0 = make_uint4(f2bf2(areg[0].x, areg[0].y), f2bf2(areg[0].z, areg[0].w),
                                  f2bf2(areg[1].x, areg[1].y), f2bf2(areg[1].z, areg[1].w));
            uint4 u1 = make_uint4(f2bf2(areg[2].x, areg[2].y), f2bf2(areg[2].z, areg[2].w),
                                  f2bf2(areg[3].x, areg[3].y), f2bf2(areg[3].z, areg[3].w));
            *(uint4*)&As[am * 20 + ahp]     = u0;
            *(uint4*)&As[am * 20 + ahp + 4] = u1;
        } else {
            *(uint4*)&As[am * 20 + ahp]     = areg1[0];
            *(uint4*)&As[am * 20 + ahp + 4] = areg1[1];
        }
        // pack B pairs along k: low = row 2bkp, high = row 2bkp+1
        uint4 v0 = make_uint4(f2bf2(breg[0].x, breg[2].x), f2bf2(breg[0].y, breg[2].y),
                              f2bf2(breg[0].z, breg[2].z), f2bf2(breg[0].w, breg[2].w));
        uint4 v1 = make_uint4(f2bf2(breg[1].x, breg[3].x), f2bf2(breg[1].y, breg[3].y),
                              f2bf2(breg[1].z, breg[3].z), f2bf2(breg[1].w, breg[3].w));
        *(uint4*)&Bs[bkp * 132 + bn]     = v0;
        *(uint4*)&Bs[bkp * 132 + bn + 4] = v1;
    };
    int r = lane >> 2, c = lane & 3;
    auto compute = [&]() {
        #pragma unroll
        for (int kk = 0; kk < 16; kk += 8) {
            uint32_t af[2][4], bf[8][2];
            #pragma unroll
            for (int mt = 0; mt < 2; mt++) {
                int m0 = wm * 32 + mt * 16 + r;
                af[mt][0] = As[m0 * 20 + kk + c];
                af[mt][1] = As[(m0 + 8) * 20 + kk + c];
                af[mt][2] = As[m0 * 20 + kk + c + 4];
                af[mt][3] = As[(m0 + 8) * 20 + kk + c + 4];
            }
            #pragma unroll
            for (int nt = 0; nt < 8; nt++) {
                int n0 = wn * 64 + nt * 8 + r;
                bf[nt][0] = Bs[(kk + c) * 132 + n0];
                bf[nt][1] = Bs[(kk + c + 4) * 132 + n0];
            }
            #pragma unroll
            for (int mt = 0; mt < 2; mt++)
                #pragma unroll
                for (int nt = 0; nt < 8; nt++)
                    mma16(acc[mt][nt], af[mt], bf[nt]);
        }
    };

    ldg(0);
    sts();
    __syncthreads();
    #pragma unroll 1
    for (int t = 1; t < 8; t++) {
        ldg(t * 32);
        compute();
        __syncthreads();
        sts();
        __syncthreads();
    }
    compute();

    // epilogue: scale rows by dinv, pack bf16x2 pairs (cols 2c,2c+1)
    constexpr int NU = N / 2;
    #pragma unroll
    for (int mt = 0; mt < 2; mt++) {
        int gr = row0 + wm * 32 + mt * 16 + r;
        bool ok0 = gr < M, ok1 = (gr + 8) < M;
        float dv0 = ok0 ? g_dinv[gr] : 0.0f;
        float dv1 = ok1 ? g_dinv[gr + 8] : 0.0f;
        #pragma unroll
        for (int nt = 0; nt < 8; nt++) {
            int gcu = (col0 + wn * 64 + nt * 8) / 2 + c;
            if (ok0)
                C[(size_t)gr * NU + gcu] =
                    f2bf2(acc[mt][nt][0] * dv0, acc[mt][nt][1] * dv0);
            if (ok1)
                C[(size_t)(gr + 8) * NU + gcu] =
                    f2bf2(acc[mt][nt][2] * dv1, acc[mt][nt][3] * dv1);
        }
    }
}

// ---------------- aggregation over bf16-packed h, bucket adjacency ----------
// out[v] = relu(dinv[v] * (h[v] + sum_{s in N(v)} h[s]) + b)
template<int LAYER>
__global__ void agg_kernel(const float* __restrict__ bias,
                           const int* __restrict__ batch) {
    constexpr int NA = (LAYER == 0) ? 8 : 4;
    int w    = (blockIdx.x * blockDim.x + threadIdx.x) >> 5;
    int lane = threadIdx.x & 31;
    if (w >= N_NODES) return;
    float dv = g_dinv[w];
    float acc[NA];
    #pragma unroll
    for (int j = 0; j < NA; j++) acc[j] = 0.0f;
    int deg = min(g_cnt[w], BSTRIDE);
    const int* bk = g_bucket + (size_t)w * BSTRIDE;

    if (LAYER == 0) {
        const uint4* h = (const uint4*)g_h1b;
        uint4 u = h[(size_t)w * 32 + lane];      // self term
        addbf2(acc + 0, u.x); addbf2(acc + 2, u.y);
        addbf2(acc + 4, u.z); addbf2(acc + 6, u.w);
        int e = 0;
        for (; e + 4 <= deg; e += 4) {
            int s0 = bk[e], s1 = bk[e + 1], s2 = bk[e + 2], s3 = bk[e + 3];
            uint4 u0 = h[(size_t)s0 * 32 + lane];
            uint4 u1 = h[(size_t)s1 * 32 + lane];
            uint4 u2 = h[(size_t)s2 * 32 + lane];
            uint4 u3 = h[(size_t)s3 * 32 + lane];
            addbf2(acc + 0, u0.x); addbf2(acc + 2, u0.y);
            addbf2(acc + 4, u0.z); addbf2(acc + 6, u0.w);
            addbf2(acc + 0, u1.x); addbf2(acc + 2, u1.y);
            addbf2(acc + 4, u1.z); addbf2(acc + 6, u1.w);
            addbf2(acc + 0, u2.x); addbf2(acc + 2, u2.y);
            addbf2(acc + 4, u2.z); addbf2(acc + 6, u2.w);
            addbf2(acc + 0, u3.x); addbf2(acc + 2, u3.y);
            addbf2(acc + 4, u3.z); addbf2(acc + 6, u3.w);
        }
        for (; e < deg; e++) {
            uint4 uu = h[(size_t)bk[e] * 32 + lane];
            addbf2(acc + 0, uu.x); addbf2(acc + 2, uu.y);
            addbf2(acc + 4, uu.z); addbf2(acc + 6, uu.w);
        }
        float o[8];
        #pragma unroll
        for (int j = 0; j < 8; j++)
            o[j] = fmaxf(dv * acc[j] + bias[lane * 8 + j], 0.0f);
        // store packed bf16 (pairs of consecutive features) for gemm2
        g_a1b[(size_t)w * 32 + lane] =
            make_uint4(f2bf2(o[0], o[1]), f2bf2(o[2], o[3]),
                       f2bf2(o[4], o[5]), f2bf2(o[6], o[7]));
    } else {
        const uint2* h = (const uint2*)g_h2b;
        uint2 u = h[(size_t)w * 32 + lane];
        addbf2(acc + 0, u.x); addbf2(acc + 2, u.y);
        int e = 0;
        for (; e + 4 <= deg; e += 4) {
            int s0 = bk[e], s1 = bk[e + 1], s2 = bk[e + 2], s3 = bk[e + 3];
            uint2 u0 = h[(size_t)s0 * 32 + lane];
            uint2 u1 = h[(size_t)s1 * 32 + lane];
            uint2 u2 = h[(size_t)s2 * 32 + lane];
            uint2 u3 = h[(size_t)s3 * 32 + lane];
            addbf2(acc + 0, u0.x); addbf2(acc + 2, u0.y);
            addbf2(acc + 0, u1.x); addbf2(acc + 2, u1.y);
            addbf2(acc + 0, u2.x); addbf2(acc + 2, u2.y);
            addbf2(acc + 0, u3.x); addbf2(acc + 2, u3.y);
        }
        for (; e < deg; e++) {
            uint2 uu = h[(size_t)bk[e] * 32 + lane];
            addbf2(acc + 0, uu.x); addbf2(acc + 2, uu.y);
        }
        int g = batch[w];
        #pragma unroll
        for (int j = 0; j < 4; j++) {
            float v = fmaxf(dv * acc[j] + bias[lane * 4 + j], 0.0f);
            atomicAdd(&g_pool[g * D2 + lane * 4 + j], v);
        }
        if (lane == 0) atomicAdd(&g_pcnt[g], 1.0f);
    }
}

// ---------------- MLP head ----------------
__global__ void k_head(const float* __restrict__ Wl1, const float* __restrict__ bl1,
                       const float* __restrict__ Wl2, const float* __restrict__ bl2,
                       float* __restrict__ out) {
    __shared__ float gv[128];
    __shared__ float hid[64];
    int g = blockIdx.x, t = threadIdx.x;
    float cgt = fmaxf(g_pcnt[g], 1.0f);
    gv[t] = g_pool[g * D2 + t] / cgt;
    __syncthreads();
    if (t < 64) {
        float s = bl1[t];
        #pragma unroll 4
        for (int k = 0; k < 128; k++) s += gv[k] * Wl1[k * 64 + t];
        hid[t] = fmaxf(s, 0.0f);
    }
    __syncthreads();
    if (t == 0) {
        float s = bl2[0];
        #pragma unroll 4
        for (int k = 0; k < 64; k++) s += hid[k] * Wl2[k];
        out[g] = 1.0f / (1.0f + expf(-s));
    }
}

// ---------------- launch ----------------
extern "C" void kernel_launch(void* const* d_in, const int* in_sizes, int n_in,
                              void* d_out, int out_size) {
    const float* x    = (const float*)d_in[0];
    const int*   ei   = (const int*)d_in[1];
    const int*   bat  = (const int*)d_in[2];
    const float* W1   = (const float*)d_in[3];
    const float* b1   = (const float*)d_in[4];
    const float* W2   = (const float*)d_in[5];
    const float* b2   = (const float*)d_in[6];
    const float* Wl1  = (const float*)d_in[7];
    const float* bl1  = (const float*)d_in[8];
    const float* Wl2  = (const float*)d_in[9];
    const float* bl2  = (const float*)d_in[10];
    float* out = (float*)d_out;

    cudaStream_t s1;
    cudaEvent_t evA, evDinv, evCsr;
    cudaStreamCreateWithFlags(&s1, cudaStreamNonBlocking);
    cudaEventCreateWithFlags(&evA,    cudaEventDisableTiming);
    cudaEventCreateWithFlags(&evDinv, cudaEventDisableTiming);
    cudaEventCreateWithFlags(&evCsr,  cudaEventDisableTiming);

    cudaEventRecord(evA, 0);
    cudaStreamWaitEvent(s1, evA, 0);

    // side branch: degree count -> dinv -> bucket fill
    k_init<<<(N_NODES + 255) / 256, 256, 0, s1>>>();
    k_cnt<<<(N_EDGES / 4 + 255) / 256, 256, 0, s1>>>(ei);
    k_dinv<<<(N_NODES + 255) / 256, 256, 0, s1>>>();
    cudaEventRecord(evDinv, s1);
    k_fill<<<(N_EDGES + 255) / 256, 256, 0, s1>>>(ei);
    cudaEventRecord(evCsr, s1);

    // main branch
    cudaStreamWaitEvent(0, evDinv, 0);
    {
        dim3 grid((N_NODES + 127) / 128, D1 / 128);
        gemm_bf<0><<<grid, 256>>>(x, W1);
    }
    cudaStreamWaitEvent(0, evCsr, 0);
    agg_kernel<0><<<(N_NODES * 32 + 255) / 256, 256>>>(b1, nullptr);

    {
        dim3 grid((N_NODES + 127) / 128, D2 / 128);
        gemm_bf<1><<<grid, 256>>>(nullptr, W2);
    }
    agg_kernel<1><<<(N_NODES * 32 + 255) / 256, 256>>>(b2, bat);

    k_head<<<NUM_G, 128>>>(Wl1, bl1, Wl2, bl2, out);
}

// round 10
// speedup vs baseline: 1.1645x; 1.0133x over previous
#include <cuda_runtime.h>
#include <math.h>
#include <stdint.h>

#define N_NODES  20000
#define N_EDGES  320000
#define NUM_G    64
#define D1       256
#define D2       128
#define BSTRIDE  96      // bucket slots per node; Poisson(16) => P(deg>=96) ~ 0

// ---------------- scratch (device globals) -------------
__device__ float g_dinv[N_NODES];
__device__ int   g_cursor[N_NODES];               // doubles as degree count
__device__ int   g_bucket[(size_t)N_NODES * BSTRIDE];
__device__ uint4 g_h1b[(size_t)N_NODES * (D1 / 8)];  // bf16x2-packed x@W1 (UNscaled)
__device__ uint4 g_a1b[(size_t)N_NODES * (D1 / 8)];  // bf16x2-packed relu(...)
__device__ uint2 g_h2b[(size_t)N_NODES * (D2 / 4)];  // bf16x2-packed dinv*(a1@W2)
__device__ float g_pool[NUM_G * D2];
__device__ float g_pcnt[NUM_G];

// ---------------- helpers ----------------
__device__ __forceinline__ uint32_t f2bf2(float lo, float hi) {
    uint32_t r;
    asm("cvt.rn.bf16x2.f32 %0, %1, %2;" : "=r"(r) : "f"(hi), "f"(lo));
    return r;
}
__device__ __forceinline__ void addbf2(float* a, uint32_t u) {
    a[0] += __uint_as_float(u << 16);
    a[1] += __uint_as_float(u & 0xffff0000u);
}
__device__ __forceinline__ void fmabf2(float* a, uint32_t u, float w) {
    a[0] = fmaf(w, __uint_as_float(u << 16), a[0]);
    a[1] = fmaf(w, __uint_as_float(u & 0xffff0000u), a[1]);
}

// ---------------- init ----------------
__global__ void k_init() {
    int i = blockIdx.x * blockDim.x + threadIdx.x;
    if (i < N_NODES) g_cursor[i] = 0;
    if (i < NUM_G * D2) g_pool[i] = 0.0f;
    if (i < NUM_G) g_pcnt[i] = 0.0f;
}

// ---------------- bucket fill (cursor ends up = degree) ----------------
__global__ void k_fill(const int* __restrict__ ei) {
    int e = blockIdx.x * blockDim.x + threadIdx.x;
    if (e < N_EDGES) {
        int d = ei[N_EDGES + e];
        int pos = atomicAdd(&g_cursor[d], 1);
        if (pos < BSTRIDE) g_bucket[(size_t)d * BSTRIDE + pos] = ei[e];
    }
}

__global__ void k_dinv() {
    int i = blockIdx.x * blockDim.x + threadIdx.x;
    if (i < N_NODES) g_dinv[i] = rsqrtf((float)(g_cursor[i] + 1));  // +1 self loop
}

// ---------------- bf16 tensor-core GEMM (m16n8k16) ----------------
__device__ __forceinline__ void mma16(float* d, const uint32_t* a, const uint32_t* b) {
    asm volatile(
        "mma.sync.aligned.m16n8k16.row.col.f32.bf16.bf16.f32 "
        "{%0,%1,%2,%3},{%4,%5,%6,%7},{%8,%9},{%0,%1,%2,%3};"
        : "+f"(d[0]), "+f"(d[1]), "+f"(d[2]), "+f"(d[3])
        : "r"(a[0]), "r"(a[1]), "r"(a[2]), "r"(a[3]), "r"(b[0]), "r"(b[1]));
}

// BM=128, BN=128, BK=32, 256 threads = 8 warps (4 x 2), warp tile 32x64.
// LAYER 0: A = x (fp32), C = g_h1b, NO row scaling (starts with zero deps).
// LAYER 1: A = g_a1b (bf16), C = g_h2b, rows scaled by dinv.
template<int LAYER>
__global__ __launch_bounds__(256, 2) void gemm_bf(const float* __restrict__ Ain,
                                                  const float* __restrict__ Bw) {
    constexpr int K = 256;
    constexpr int N = (LAYER == 0) ? 256 : 128;
    constexpr int M = N_NODES;
    uint32_t* C = (LAYER == 0) ? (uint32_t*)g_h1b : (uint32_t*)g_h2b;

    __shared__ uint32_t As[128 * 20];   // [m][kpair], kpair 0..15, stride 20
    __shared__ uint32_t Bs[16 * 132];   // [kpair][n],  n 0..127,  stride 132

    int tid = threadIdx.x, lane = tid & 31, warp = tid >> 5;
    int wm = warp & 3, wn = warp >> 2;
    int row0 = blockIdx.x * 128, col0 = blockIdx.y * 128;

    int am = tid >> 1, ahp = (tid & 1) * 8;
    int bkp = tid >> 4, bn = (tid & 15) * 8;

    float acc[2][8][4];
    #pragma unroll
    for (int mt = 0; mt < 2; mt++)
        #pragma unroll
        for (int nt = 0; nt < 8; nt++)
            #pragma unroll
            for (int i = 0; i < 4; i++) acc[mt][nt][i] = 0.0f;

    bool aok = (row0 + am) < M;
    float4 areg[4];
    uint4  areg1[2];
    float4 breg[4];

    const float* aptr0 = Ain + (size_t)(row0 + am) * K + ahp * 2;
    const uint4* aptr1 = g_a1b + (size_t)(row0 + am) * 32 + (tid & 1) * 2;
    const float* bptr = Bw + (size_t)(2 * bkp) * N + col0 + bn;

    auto ldg = [&](int k0) {
        if (LAYER == 0) {
            #pragma unroll
            for (int j = 0; j < 4; j++)
                areg[j] = aok ? *(const float4*)(aptr0 + k0 + 4 * j)
                              : make_float4(0.f, 0.f, 0.f, 0.f);
        } else {
            #pragma unroll
            for (int j = 0; j < 2; j++)
                areg1[j] = aok ? aptr1[k0 / 8 + j]
                               : make_uint4(0u, 0u, 0u, 0u);
        }
        const float* bp = bptr + (size_t)k0 * N;
        breg[0] = *(const float4*)(bp);
        breg[1] = *(const float4*)(bp + 4);
        breg[2] = *(const float4*)(bp + N);
        breg[3] = *(const float4*)(bp + N + 4);
    };
    auto sts = [&]() {
        if (LAYER == 0) {
            uint4 u0 = make_uint4(f2bf2(areg[0].x, areg[0].y), f2bf2(areg[0].z, areg[0].w),
                                  f2bf2(areg[1].x, areg[1].y), f2bf2(areg[1].z, areg[1].w));
            uint4 u1 = make_uint4(f2bf2(areg[2].x, areg[2].y), f2bf2(areg[2].z, areg[2].w),
                                  f2bf2(areg[3].x, areg[3].y), f2bf2(areg[3].z, areg[3].w));
            *(uint4*)&As[am * 20 + ahp]     = u0;
            *(uint4*)&As[am * 20 + ahp + 4] = u1;
        } else {
            *(uint4*)&As[am * 20 + ahp]     = areg1[0];
            *(uint4*)&As[am * 20 + ahp + 4] = areg1[1];
        }
        uint4 v0 = make_uint4(f2bf2(breg[0].x, breg[2].x), f2bf2(breg[0].y, breg[2].y),
                              f2bf2(breg[0].z, breg[2].z), f2bf2(breg[0].w, breg[2].w));
        uint4 v1 = make_uint4(f2bf2(breg[1].x, breg[3].x), f2bf2(breg[1].y, breg[3].y),
                              f2bf2(breg[1].z, breg[3].z), f2bf2(breg[1].w, breg[3].w));
        *(uint4*)&Bs[bkp * 132 + bn]     = v0;
        *(uint4*)&Bs[bkp * 132 + bn + 4] = v1;
    };
    int r = lane >> 2, c = lane & 3;
    auto compute = [&]() {
        #pragma unroll
        for (int kk = 0; kk < 16; kk += 8) {
            uint32_t af[2][4], bf[8][2];
            #pragma unroll
            for (int mt = 0; mt < 2; mt++) {
                int m0 = wm * 32 + mt * 16 + r;
                af[mt][0] = As[m0 * 20 + kk + c];
                af[mt][1] = As[(m0 + 8) * 20 + kk + c];
                af[mt][2] = As[m0 * 20 + kk + c + 4];
                af[mt][3] = As[(m0 + 8) * 20 + kk + c + 4];
            }
            #pragma unroll
            for (int nt = 0; nt < 8; nt++) {
                int n0 = wn * 64 + nt * 8 + r;
                bf[nt][0] = Bs[(kk + c) * 132 + n0];
                bf[nt][1] = Bs[(kk + c + 4) * 132 + n0];
            }
            #pragma unroll
            for (int mt = 0; mt < 2; mt++)
                #pragma unroll
                for (int nt = 0; nt < 8; nt++)
                    mma16(acc[mt][nt], af[mt], bf[nt]);
        }
    };

    ldg(0);
    sts();
    __syncthreads();
    #pragma unroll 1
    for (int t = 1; t < 8; t++) {
        ldg(t * 32);
        compute();
        __syncthreads();
        sts();
        __syncthreads();
    }
    compute();

    constexpr int NU = N / 2;
    #pragma unroll
    for (int mt = 0; mt < 2; mt++) {
        int gr = row0 + wm * 32 + mt * 16 + r;
        bool ok0 = gr < M, ok1 = (gr + 8) < M;
        float dv0 = 1.0f, dv1 = 1.0f;
        if (LAYER == 1) {
            dv0 = ok0 ? g_dinv[gr] : 0.0f;
            dv1 = ok1 ? g_dinv[gr + 8] : 0.0f;
        }
        #pragma unroll
        for (int nt = 0; nt < 8; nt++) {
            int gcu = (col0 + wn * 64 + nt * 8) / 2 + c;
            if (ok0)
                C[(size_t)gr * NU + gcu] =
                    f2bf2(acc[mt][nt][0] * dv0, acc[mt][nt][1] * dv0);
            if (ok1)
                C[(size_t)(gr + 8) * NU + gcu] =
                    f2bf2(acc[mt][nt][2] * dv1, acc[mt][nt][3] * dv1);
        }
    }
}

// ---------------- aggregation ----------------
// LAYER 0 (h1 unscaled): out[v] = relu(dv*(dv*h[v] + sum_s dinv[s]*h[s]) + b)
// LAYER 1 (h2 pre-scaled): out[v] = relu(dv*(h[v] + sum_s h[s]) + b) -> pool
template<int LAYER>
__global__ void agg_kernel(const float* __restrict__ bias,
                           const int* __restrict__ batch) {
    constexpr int NA = (LAYER == 0) ? 8 : 4;
    int w    = (blockIdx.x * blockDim.x + threadIdx.x) >> 5;
    int lane = threadIdx.x & 31;
    if (w >= N_NODES) return;
    float dv = g_dinv[w];
    float acc[NA];
    #pragma unroll
    for (int j = 0; j < NA; j++) acc[j] = 0.0f;
    int deg = min(g_cursor[w], BSTRIDE);
    const int* bk = g_bucket + (size_t)w * BSTRIDE;

    if (LAYER == 0) {
        const uint4* h = (const uint4*)g_h1b;
        uint4 u = h[(size_t)w * 32 + lane];      // self term, weight dv
        fmabf2(acc + 0, u.x, dv); fmabf2(acc + 2, u.y, dv);
        fmabf2(acc + 4, u.z, dv); fmabf2(acc + 6, u.w, dv);
        int e = 0;
        for (; e + 4 <= deg; e += 4) {
            int s0 = bk[e], s1 = bk[e + 1], s2 = bk[e + 2], s3 = bk[e + 3];
            float w0 = g_dinv[s0], w1 = g_dinv[s1];
            float w2 = g_dinv[s2], w3 = g_dinv[s3];
            uint4 u0 = h[(size_t)s0 * 32 + lane];
            uint4 u1 = h[(size_t)s1 * 32 + lane];
            uint4 u2 = h[(size_t)s2 * 32 + lane];
            uint4 u3 = h[(size_t)s3 * 32 + lane];
            fmabf2(acc + 0, u0.x, w0); fmabf2(acc + 2, u0.y, w0);
            fmabf2(acc + 4, u0.z, w0); fmabf2(acc + 6, u0.w, w0);
            fmabf2(acc + 0, u1.x, w1); fmabf2(acc + 2, u1.y, w1);
            fmabf2(acc + 4, u1.z, w1); fmabf2(acc + 6, u1.w, w1);
            fmabf2(acc + 0, u2.x, w2); fmabf2(acc + 2, u2.y, w2);
            fmabf2(acc + 4, u2.z, w2); fmabf2(acc + 6, u2.w, w2);
            fmabf2(acc + 0, u3.x, w3); fmabf2(acc + 2, u3.y, w3);
            fmabf2(acc + 4, u3.z, w3); fmabf2(acc + 6, u3.w, w3);
        }
        for (; e < deg; e++) {
            int s = bk[e];
            float ws = g_dinv[s];
            uint4 uu = h[(size_t)s * 32 + lane];
            fmabf2(acc + 0, uu.x, ws); fmabf2(acc + 2, uu.y, ws);
            fmabf2(acc + 4, uu.z, ws); fmabf2(acc + 6, uu.w, ws);
        }
        float o[8];
        #pragma unroll
        for (int j = 0; j < 8; j++)
            o[j] = fmaxf(dv * acc[j] + bias[lane * 8 + j], 0.0f);
        g_a1b[(size_t)w * 32 + lane] =
            make_uint4(f2bf2(o[0], o[1]), f2bf2(o[2], o[3]),
                       f2bf2(o[4], o[5]), f2bf2(o[6], o[7]));
    } else {
        const uint2* h = (const uint2*)g_h2b;
        uint2 u = h[(size_t)w * 32 + lane];
        addbf2(acc + 0, u.x); addbf2(acc + 2, u.y);
        int e = 0;
        for (; e + 4 <= deg; e += 4) {
            int s0 = bk[e], s1 = bk[e + 1], s2 = bk[e + 2], s3 = bk[e + 3];
            uint2 u0 = h[(size_t)s0 * 32 + lane];
            uint2 u1 = h[(size_t)s1 * 32 + lane];
            uint2 u2 = h[(size_t)s2 * 32 + lane];
            uint2 u3 = h[(size_t)s3 * 32 + lane];
            addbf2(acc + 0, u0.x); addbf2(acc + 2, u0.y);
            addbf2(acc + 0, u1.x); addbf2(acc + 2, u1.y);
            addbf2(acc + 0, u2.x); addbf2(acc + 2, u2.y);
            addbf2(acc + 0, u3.x); addbf2(acc + 2, u3.y);
        }
        for (; e < deg; e++) {
            uint2 uu = h[(size_t)bk[e] * 32 + lane];
            addbf2(acc + 0, uu.x); addbf2(acc + 2, uu.y);
        }
        int g = batch[w];
        #pragma unroll
        for (int j = 0; j < 4; j++) {
            float v = fmaxf(dv * acc[j] + bias[lane * 4 + j], 0.0f);
            atomicAdd(&g_pool[g * D2 + lane * 4 + j], v);
        }
        if (lane == 0) atomicAdd(&g_pcnt[g], 1.0f);
    }
}

// ---------------- MLP head ----------------
__global__ void k_head(const float* __restrict__ Wl1, const float* __restrict__ bl1,
                       const float* __restrict__ Wl2, const float* __restrict__ bl2,
                       float* __restrict__ out) {
    __shared__ float gv[128];
    __shared__ float hid[64];
    int g = blockIdx.x, t = threadIdx.x;
    float cgt = fmaxf(g_pcnt[g], 1.0f);
    gv[t] = g_pool[g * D2 + t] / cgt;
    __syncthreads();
    if (t < 64) {
        float s = bl1[t];
        #pragma unroll 4
        for (int k = 0; k < 128; k++) s += gv[k] * Wl1[k * 64 + t];
        hid[t] = fmaxf(s, 0.0f);
    }
    __syncthreads();
    if (t == 0) {
        float s = bl2[0];
        #pragma unroll 4
        for (int k = 0; k < 64; k++) s += hid[k] * Wl2[k];
        out[g] = 1.0f / (1.0f + expf(-s));
    }
}

// ---------------- launch ----------------
extern "C" void kernel_launch(void* const* d_in, const int* in_sizes, int n_in,
                              void* d_out, int out_size) {
    const float* x    = (const float*)d_in[0];
    const int*   ei   = (const int*)d_in[1];
    const int*   bat  = (const int*)d_in[2];
    const float* W1   = (const float*)d_in[3];
    const float* b1   = (const float*)d_in[4];
    const float* W2   = (const float*)d_in[5];
    const float* b2   = (const float*)d_in[6];
    const float* Wl1  = (const float*)d_in[7];
    const float* bl1  = (const float*)d_in[8];
    const float* Wl2  = (const float*)d_in[9];
    const float* bl2  = (const float*)d_in[10];
    float* out = (float*)d_out;

    cudaStream_t s1;
    cudaEvent_t evA, evCsr;
    cudaStreamCreateWithFlags(&s1, cudaStreamNonBlocking);
    cudaEventCreateWithFlags(&evA,   cudaEventDisableTiming);
    cudaEventCreateWithFlags(&evCsr, cudaEventDisableTiming);

    cudaEventRecord(evA, 0);
    cudaStreamWaitEvent(s1, evA, 0);

    // side branch: init -> fill (cursor becomes degree) -> dinv
    k_init<<<(N_NODES + 255) / 256, 256, 0, s1>>>();
    k_fill<<<(N_EDGES + 255) / 256, 256, 0, s1>>>(ei);
    k_dinv<<<(N_NODES + 255) / 256, 256, 0, s1>>>();
    cudaEventRecord(evCsr, s1);

    // main branch: gemm1 starts immediately (no dependency on preprocessing)
    {
        dim3 grid((N_NODES + 127) / 128, D1 / 128);
        gemm_bf<0><<<grid, 256>>>(x, W1);
    }
    cudaStreamWaitEvent(0, evCsr, 0);
    agg_kernel<0><<<(N_NODES * 32 + 255) / 256, 256>>>(b1, nullptr);

    {
        dim3 grid((N_NODES + 127) / 128, D2 / 128);
        gemm_bf<1><<<grid, 256>>>(nullptr, W2);
    }
    agg_kernel<1><<<(N_NODES * 32 + 255) / 256, 256>>>(b2, bat);

    k_head<<<NUM_G, 128>>>(Wl1, bl1, Wl2, bl2, out);
}

// round 12
// speedup vs baseline: 1.1803x; 1.0135x over previous
#include <cuda_runtime.h>
#include <math.h>
#include <stdint.h>

#define N_NODES  20000
#define N_EDGES  320000
#define NUM_G    64
#define D1       256
#define D2       128
#define BSTRIDE  96      // bucket slots per node; Poisson(16) => P(deg>=96) ~ 0

// ---------------- scratch (device globals) -------------
__device__ float    g_dinv[N_NODES];
__device__ int      g_cursor[N_NODES];            // doubles as degree count
__device__ int      g_bucket[(size_t)N_NODES * BSTRIDE];
__device__ uint32_t g_xb[(size_t)N_NODES * 128];  // bf16x2-packed x
__device__ uint32_t g_wt1[256 * 128];             // bf16x2 W1^T [n][kpair]
__device__ uint32_t g_wt2[128 * 128];             // bf16x2 W2^T [n][kpair]
__device__ uint4    g_h1b[(size_t)N_NODES * (D1 / 8)];  // x@W1 (UNscaled)
__device__ uint4    g_a1b[(size_t)N_NODES * (D1 / 8)];  // relu(...)
__device__ uint2    g_h2b[(size_t)N_NODES * (D2 / 4)];  // dinv*(a1@W2)
__device__ float    g_pool[NUM_G * D2];
__device__ float    g_pcnt[NUM_G];

// ---------------- helpers ----------------
__device__ __forceinline__ uint32_t f2bf2(float lo, float hi) {
    uint32_t r;
    asm("cvt.rn.bf16x2.f32 %0, %1, %2;" : "=r"(r) : "f"(hi), "f"(lo));
    return r;
}
__device__ __forceinline__ void addbf2(float* a, uint32_t u) {
    a[0] += __uint_as_float(u << 16);
    a[1] += __uint_as_float(u & 0xffff0000u);
}
__device__ __forceinline__ void fmabf2(float* a, uint32_t u, float w) {
    a[0] = fmaf(w, __uint_as_float(u << 16), a[0]);
    a[1] = fmaf(w, __uint_as_float(u & 0xffff0000u), a[1]);
}

// ---------------- init ----------------
__global__ void k_init() {
    int i = blockIdx.x * blockDim.x + threadIdx.x;
    if (i < N_NODES) g_cursor[i] = 0;
    if (i < NUM_G * D2) g_pool[i] = 0.0f;
    if (i < NUM_G) g_pcnt[i] = 0.0f;
}

// ---------------- conversions ----------------
__global__ void k_cvt_x(const float* __restrict__ x) {
    int i = blockIdx.x * blockDim.x + threadIdx.x;
    if (i < N_NODES * 128) {
        float2 v = ((const float2*)x)[i];
        g_xb[i] = f2bf2(v.x, v.y);
    }
}
// W [K][N] fp32 row-major -> WT [n][kpair] bf16x2 (kpair = features 2kp,2kp+1)
__global__ void k_cvt_w(const float* __restrict__ W1, const float* __restrict__ W2) {
    int i = blockIdx.x * blockDim.x + threadIdx.x;
    if (i < 256 * 128) {                       // W1: n 0..255, kp 0..127
        int n = i & 255, kp = i >> 8;
        g_wt1[(size_t)n * 128 + kp] = f2bf2(W1[(2 * kp) * 256 + n],
                                            W1[(2 * kp + 1) * 256 + n]);
    } else if (i < 256 * 128 + 128 * 128) {    // W2: n 0..127, kp 0..127
        int j = i - 256 * 128;
        int n = j & 127, kp = j >> 7;
        g_wt2[(size_t)n * 128 + kp] = f2bf2(W2[(2 * kp) * 128 + n],
                                            W2[(2 * kp + 1) * 128 + n]);
    }
}

// ---------------- bucket fill (cursor ends up = degree) ----------------
__global__ void k_fill(const int* __restrict__ ei) {
    int e = blockIdx.x * blockDim.x + threadIdx.x;
    if (e < N_EDGES) {
        int d = ei[N_EDGES + e];
        int pos = atomicAdd(&g_cursor[d], 1);
        if (pos < BSTRIDE) g_bucket[(size_t)d * BSTRIDE + pos] = ei[e];
    }
}

__global__ void k_dinv() {
    int i = blockIdx.x * blockDim.x + threadIdx.x;
    if (i < N_NODES) g_dinv[i] = rsqrtf((float)(g_cursor[i] + 1));  // +1 self loop
}

// ---------------- bf16 tensor-core GEMM (m16n8k16) ----------------
__device__ __forceinline__ void mma16(float* d, const uint32_t* a, const uint32_t* b) {
    asm volatile(
        "mma.sync.aligned.m16n8k16.row.col.f32.bf16.bf16.f32 "
        "{%0,%1,%2,%3},{%4,%5,%6,%7},{%8,%9},{%0,%1,%2,%3};"
        : "+f"(d[0]), "+f"(d[1]), "+f"(d[2]), "+f"(d[3])
        : "r"(a[0]), "r"(a[1]), "r"(a[2]), "r"(a[3]), "r"(b[0]), "r"(b[1]));
}

// All-bf16 GEMM. BM=128, BN=128, BK=32 (16 kpairs), 512 threads = 16 warps (4x4),
// warp tile 32x32. A: [M][128] uint32 kpairs. BT: [N][128] uint32 kpairs.
// All operand pointers resolved from __device__ globals INSIDE device code.
// LAYER 0: A=g_xb, BT=g_wt1, N=256, C=g_h1b, no scaling.
// LAYER 1: A=g_a1b, BT=g_wt2, N=128, C=g_h2b, rows scaled by dinv.
template<int LAYER>
__global__ __launch_bounds__(512, 2) void gemm_bf() {
    constexpr int N = (LAYER == 0) ? 256 : 128;
    constexpr int M = N_NODES;
    constexpr int KP = 128;          // kpairs per row
    const uint32_t* A  = (LAYER == 0) ? g_xb : (const uint32_t*)g_a1b;
    const uint32_t* BT = (LAYER == 0) ? g_wt1 : g_wt2;
    uint32_t* C = (LAYER == 0) ? (uint32_t*)g_h1b : (uint32_t*)g_h2b;

    __shared__ uint32_t As[2][128 * 20];   // [m][kpair], stride 20
    __shared__ uint32_t Bs[2][128 * 20];   // [n][kpair], stride 20

    int tid = threadIdx.x, lane = tid & 31, warp = tid >> 5;
    int wm = warp & 3, wn = warp >> 2;     // 4 x 4
    int row0 = blockIdx.x * 128, col0 = blockIdx.y * 128;

    int crow = tid >> 2, cch = (tid & 3) * 4;   // copy: row, uint32-chunk
    bool aok = (row0 + crow) < M;
    const uint32_t* aptr = A  + (size_t)(row0 + crow) * KP + cch;
    const uint32_t* bptr = BT + (size_t)(col0 + crow) * KP + cch;

    float acc[2][4][4];
    #pragma unroll
    for (int mt = 0; mt < 2; mt++)
        #pragma unroll
        for (int nt = 0; nt < 4; nt++)
            #pragma unroll
            for (int i = 0; i < 4; i++) acc[mt][nt][i] = 0.0f;

    uint4 av, bv;
    auto ldg = [&](int kp0) {
        av = aok ? *(const uint4*)(aptr + kp0) : make_uint4(0u, 0u, 0u, 0u);
        bv = *(const uint4*)(bptr + kp0);
    };
    auto sts = [&](int buf) {
        *(uint4*)&As[buf][crow * 20 + cch] = av;
        *(uint4*)&Bs[buf][crow * 20 + cch] = bv;
    };
    int r = lane >> 2, c = lane & 3;
    auto compute = [&](int buf) {
        #pragma unroll
        for (int kk = 0; kk < 16; kk += 8) {
            uint32_t af[2][4], bf[4][2];
            #pragma unroll
            for (int mt = 0; mt < 2; mt++) {
                int m0 = wm * 32 + mt * 16 + r;
                af[mt][0] = As[buf][m0 * 20 + kk + c];
                af[mt][1] = As[buf][(m0 + 8) * 20 + kk + c];
                af[mt][2] = As[buf][m0 * 20 + kk + c + 4];
                af[mt][3] = As[buf][(m0 + 8) * 20 + kk + c + 4];
            }
            #pragma unroll
            for (int nt = 0; nt < 4; nt++) {
                int n0 = wn * 32 + nt * 8 + r;
                bf[nt][0] = Bs[buf][n0 * 20 + kk + c];
                bf[nt][1] = Bs[buf][n0 * 20 + kk + c + 4];
            }
            #pragma unroll
            for (int mt = 0; mt < 2; mt++)
                #pragma unroll
                for (int nt = 0; nt < 4; nt++)
                    mma16(acc[mt][nt], af[mt], bf[nt]);
        }
    };

    ldg(0);
    sts(0);
    __syncthreads();
    #pragma unroll 1
    for (int t = 1; t < 8; t++) {
        ldg(t * 16);                 // prefetch next tile (16 kpairs = BK 32)
        compute((t - 1) & 1);        // compute current
        sts(t & 1);                  // store prefetched into other buffer
        __syncthreads();
    }
    compute(1);

    // epilogue
    constexpr int NU = N / 2;
    #pragma unroll
    for (int mt = 0; mt < 2; mt++) {
        int gr = row0 + wm * 32 + mt * 16 + r;
        bool ok0 = gr < M, ok1 = (gr + 8) < M;
        float dv0 = 1.0f, dv1 = 1.0f;
        if (LAYER == 1) {
            dv0 = ok0 ? g_dinv[gr] : 0.0f;
            dv1 = ok1 ? g_dinv[gr + 8] : 0.0f;
        }
        #pragma unroll
        for (int nt = 0; nt < 4; nt++) {
            int gcu = (col0 + wn * 32 + nt * 8) / 2 + c;
            if (ok0)
                C[(size_t)gr * NU + gcu] =
                    f2bf2(acc[mt][nt][0] * dv0, acc[mt][nt][1] * dv0);
            if (ok1)
                C[(size_t)(gr + 8) * NU + gcu] =
                    f2bf2(acc[mt][nt][2] * dv1, acc[mt][nt][3] * dv1);
        }
    }
}

// ---------------- aggregation ----------------
// LAYER 0 (h1 unscaled): out[v] = relu(dv*(dv*h[v] + sum_s dinv[s]*h[s]) + b)
// LAYER 1 (h2 pre-scaled): out[v] = relu(dv*(h[v] + sum_s h[s]) + b) -> pool
template<int LAYER>
__global__ void agg_kernel(const float* __restrict__ bias,
                           const int* __restrict__ batch) {
    constexpr int NA = (LAYER == 0) ? 8 : 4;
    int w    = (blockIdx.x * blockDim.x + threadIdx.x) >> 5;
    int lane = threadIdx.x & 31;
    if (w >= N_NODES) return;
    float dv = g_dinv[w];
    float acc[NA];
    #pragma unroll
    for (int j = 0; j < NA; j++) acc[j] = 0.0f;
    int deg = min(g_cursor[w], BSTRIDE);
    const int* bk = g_bucket + (size_t)w * BSTRIDE;

    if (LAYER == 0) {
        const uint4* h = (const uint4*)g_h1b;
        uint4 u = h[(size_t)w * 32 + lane];
        fmabf2(acc + 0, u.x, dv); fmabf2(acc + 2, u.y, dv);
        fmabf2(acc + 4, u.z, dv); fmabf2(acc + 6, u.w, dv);
        int e = 0;
        for (; e + 4 <= deg; e += 4) {
            int s0 = bk[e], s1 = bk[e + 1], s2 = bk[e + 2], s3 = bk[e + 3];
            float w0 = g_dinv[s0], w1 = g_dinv[s1];
            float w2 = g_dinv[s2], w3 = g_dinv[s3];
            uint4 u0 = h[(size_t)s0 * 32 + lane];
            uint4 u1 = h[(size_t)s1 * 32 + lane];
            uint4 u2 = h[(size_t)s2 * 32 + lane];
            uint4 u3 = h[(size_t)s3 * 32 + lane];
            fmabf2(acc + 0, u0.x, w0); fmabf2(acc + 2, u0.y, w0);
            fmabf2(acc + 4, u0.z, w0); fmabf2(acc + 6, u0.w, w0);
            fmabf2(acc + 0, u1.x, w1); fmabf2(acc + 2, u1.y, w1);
            fmabf2(acc + 4, u1.z, w1); fmabf2(acc + 6, u1.w, w1);
            fmabf2(acc + 0, u2.x, w2); fmabf2(acc + 2, u2.y, w2);
            fmabf2(acc + 4, u2.z, w2); fmabf2(acc + 6, u2.w, w2);
            fmabf2(acc + 0, u3.x, w3); fmabf2(acc + 2, u3.y, w3);
            fmabf2(acc + 4, u3.z, w3); fmabf2(acc + 6, u3.w, w3);
        }
        for (; e < deg; e++) {
            int s = bk[e];
            float ws = g_dinv[s];
            uint4 uu = h[(size_t)s * 32 + lane];
            fmabf2(acc + 0, uu.x, ws); fmabf2(acc + 2, uu.y, ws);
            fmabf2(acc + 4, uu.z, ws); fmabf2(acc + 6, uu.w, ws);
        }
        float o[8];
        #pragma unroll
        for (int j = 0; j < 8; j++)
            o[j] = fmaxf(dv * acc[j] + bias[lane * 8 + j], 0.0f);
        g_a1b[(size_t)w * 32 + lane] =
            make_uint4(f2bf2(o[0], o[1]), f2bf2(o[2], o[3]),
                       f2bf2(o[4], o[5]), f2bf2(o[6], o[7]));
    } else {
        const uint2* h = (const uint2*)g_h2b;
        uint2 u = h[(size_t)w * 32 + lane];
        addbf2(acc + 0, u.x); addbf2(acc + 2, u.y);
        int e = 0;
        for (; e + 4 <= deg; e += 4) {
            int s0 = bk[e], s1 = bk[e + 1], s2 = bk[e + 2], s3 = bk[e + 3];
            uint2 u0 = h[(size_t)s0 * 32 + lane];
            uint2 u1 = h[(size_t)s1 * 32 + lane];
            uint2 u2 = h[(size_t)s2 * 32 + lane];
            uint2 u3 = h[(size_t)s3 * 32 + lane];
            addbf2(acc + 0, u0.x); addbf2(acc + 2, u0.y);
            addbf2(acc + 0, u1.x); addbf2(acc + 2, u1.y);
            addbf2(acc + 0, u2.x); addbf2(acc + 2, u2.y);
            addbf2(acc + 0, u3.x); addbf2(acc + 2, u3.y);
        }
        for (; e < deg; e++) {
            uint2 uu = h[(size_t)bk[e] * 32 + lane];
            addbf2(acc + 0, uu.x); addbf2(acc + 2, uu.y);
        }
        int g = batch[w];
        #pragma unroll
        for (int j = 0; j < 4; j++) {
            float v = fmaxf(dv * acc[j] + bias[lane * 4 + j], 0.0f);
            atomicAdd(&g_pool[g * D2 + lane * 4 + j], v);
        }
        if (lane == 0) atomicAdd(&g_pcnt[g], 1.0f);
    }
}

// ---------------- MLP head ----------------
__global__ void k_head(const float* __restrict__ Wl1, const float* __restrict__ bl1,
                       const float* __restrict__ Wl2, const float* __restrict__ bl2,
                       float* __restrict__ out) {
    __shared__ float gv[128];
    __shared__ float hid[64];
    int g = blockIdx.x, t = threadIdx.x;
    float cgt = fmaxf(g_pcnt[g], 1.0f);
    gv[t] = g_pool[g * D2 + t] / cgt;
    __syncthreads();
    if (t < 64) {
        float s = bl1[t];
        #pragma unroll 4
        for (int k = 0; k < 128; k++) s += gv[k] * Wl1[k * 64 + t];
        hid[t] = fmaxf(s, 0.0f);
    }
    __syncthreads();
    if (t == 0) {
        float s = bl2[0];
        #pragma unroll 4
        for (int k = 0; k < 64; k++) s += hid[k] * Wl2[k];
        out[g] = 1.0f / (1.0f + expf(-s));
    }
}

// ---------------- launch ----------------
extern "C" void kernel_launch(void* const* d_in, const int* in_sizes, int n_in,
                              void* d_out, int out_size) {
    const float* x    = (const float*)d_in[0];
    const int*   ei   = (const int*)d_in[1];
    const int*   bat  = (const int*)d_in[2];
    const float* W1   = (const float*)d_in[3];
    const float* b1   = (const float*)d_in[4];
    const float* W2   = (const float*)d_in[5];
    const float* b2   = (const float*)d_in[6];
    const float* Wl1  = (const float*)d_in[7];
    const float* bl1  = (const float*)d_in[8];
    const float* Wl2  = (const float*)d_in[9];
    const float* bl2  = (const float*)d_in[10];
    float* out = (float*)d_out;

    cudaStream_t s1;
    cudaEvent_t evA, evW, evCsr;
    cudaStreamCreateWithFlags(&s1, cudaStreamNonBlocking);
    cudaEventCreateWithFlags(&evA,   cudaEventDisableTiming);
    cudaEventCreateWithFlags(&evW,   cudaEventDisableTiming);
    cudaEventCreateWithFlags(&evCsr, cudaEventDisableTiming);

    cudaEventRecord(evA, 0);
    cudaStreamWaitEvent(s1, evA, 0);

    // side branch: weight conversion first (gemm1 needs it), then CSR build
    k_cvt_w<<<(256 * 128 + 128 * 128 + 255) / 256, 256, 0, s1>>>(W1, W2);
    cudaEventRecord(evW, s1);
    k_init<<<(N_NODES + 255) / 256, 256, 0, s1>>>();
    k_fill<<<(N_EDGES + 255) / 256, 256, 0, s1>>>(ei);
    k_dinv<<<(N_NODES + 255) / 256, 256, 0, s1>>>();
    cudaEventRecord(evCsr, s1);

    // main branch: convert x (runs concurrently with side branch)
    k_cvt_x<<<(N_NODES * 128 + 255) / 256, 256>>>(x);
    cudaStreamWaitEvent(0, evW, 0);
    {
        dim3 grid((N_NODES + 127) / 128, D1 / 128);
        gemm_bf<0><<<grid, 512>>>();
    }
    cudaStreamWaitEvent(0, evCsr, 0);
    agg_kernel<0><<<(N_NODES * 32 + 255) / 256, 256>>>(b1, nullptr);

    {
        dim3 grid((N_NODES + 127) / 128, D2 / 128);
        gemm_bf<1><<<grid, 512>>>();
    }
    agg_kernel<1><<<(N_NODES * 32 + 255) / 256, 256>>>(b2, bat);

    k_head<<<NUM_G, 128>>>(Wl1, bl1, Wl2, bl2, out);
}

// round 13
// speedup vs baseline: 1.2260x; 1.0387x over previous
#include <cuda_runtime.h>
#include <math.h>
#include <stdint.h>

#define N_NODES  20000
#define N_EDGES  320000
#define NUM_G    64
#define D1       256
#define D2       128
#define BSTRIDE  96      // bucket slots per node; Poisson(16) => P(deg>=96) ~ 0

// ---------------- scratch (device globals) -------------
__device__ float    g_dinv[N_NODES];
__device__ int      g_cursor[N_NODES];            // doubles as degree count
__device__ int      g_bucket[(size_t)N_NODES * BSTRIDE];
__device__ uint32_t g_xb[(size_t)N_NODES * 128];  // bf16x2-packed x
__device__ uint32_t g_wt1[256 * 128];             // bf16x2 W1^T [n][kpair]
__device__ uint32_t g_wt2[128 * 128];             // bf16x2 W2^T [n][kpair]
__device__ uint4    g_h1b[(size_t)N_NODES * (D1 / 8)];  // x@W1 (UNscaled)
__device__ uint4    g_a1b[(size_t)N_NODES * (D1 / 8)];  // relu(...)
__device__ uint2    g_h2b[(size_t)N_NODES * (D2 / 4)];  // dinv*(a1@W2)
__device__ float    g_pool[NUM_G * D2];
__device__ float    g_pcnt[NUM_G];

// ---------------- helpers ----------------
__device__ __forceinline__ uint32_t f2bf2(float lo, float hi) {
    uint32_t r;
    asm("cvt.rn.bf16x2.f32 %0, %1, %2;" : "=r"(r) : "f"(hi), "f"(lo));
    return r;
}
__device__ __forceinline__ void addbf2(float* a, uint32_t u) {
    a[0] += __uint_as_float(u << 16);
    a[1] += __uint_as_float(u & 0xffff0000u);
}
__device__ __forceinline__ void fmabf2(float* a, uint32_t u, float w) {
    a[0] = fmaf(w, __uint_as_float(u << 16), a[0]);
    a[1] = fmaf(w, __uint_as_float(u & 0xffff0000u), a[1]);
}
__device__ __forceinline__ void cp16(uint32_t dst, const void* src, uint32_t srcsize) {
    asm volatile("cp.async.cg.shared.global [%0], [%1], 16, %2;"
                 :: "r"(dst), "l"(src), "r"(srcsize));
}
__device__ __forceinline__ void cp_commit() {
    asm volatile("cp.async.commit_group;");
}
template<int N>
__device__ __forceinline__ void cp_wait() {
    asm volatile("cp.async.wait_group %0;" :: "n"(N));
}
__device__ __forceinline__ void ldsm4(uint32_t* r, uint32_t addr) {
    asm volatile("ldmatrix.sync.aligned.m8n8.x4.shared.b16 {%0,%1,%2,%3}, [%4];"
                 : "=r"(r[0]), "=r"(r[1]), "=r"(r[2]), "=r"(r[3]) : "r"(addr));
}

// ---------------- init ----------------
__global__ void k_init() {
    int i = blockIdx.x * blockDim.x + threadIdx.x;
    if (i < N_NODES) g_cursor[i] = 0;
    if (i < NUM_G * D2) g_pool[i] = 0.0f;
    if (i < NUM_G) g_pcnt[i] = 0.0f;
}

// ---------------- conversions ----------------
__global__ void k_cvt_x(const float* __restrict__ x) {
    int i = blockIdx.x * blockDim.x + threadIdx.x;
    if (i < N_NODES * 128) {
        float2 v = ((const float2*)x)[i];
        g_xb[i] = f2bf2(v.x, v.y);
    }
}
// W [K][N] fp32 row-major -> WT [n][kpair] bf16x2
__global__ void k_cvt_w(const float* __restrict__ W1, const float* __restrict__ W2) {
    int i = blockIdx.x * blockDim.x + threadIdx.x;
    if (i < 256 * 128) {
        int n = i & 255, kp = i >> 8;
        g_wt1[(size_t)n * 128 + kp] = f2bf2(W1[(2 * kp) * 256 + n],
                                            W1[(2 * kp + 1) * 256 + n]);
    } else if (i < 256 * 128 + 128 * 128) {
        int j = i - 256 * 128;
        int n = j & 127, kp = j >> 7;
        g_wt2[(size_t)n * 128 + kp] = f2bf2(W2[(2 * kp) * 128 + n],
                                            W2[(2 * kp + 1) * 128 + n]);
    }
}

// ---------------- bucket fill (cursor ends up = degree) ----------------
__global__ void k_fill(const int* __restrict__ ei) {
    int e = blockIdx.x * blockDim.x + threadIdx.x;
    if (e < N_EDGES) {
        int d = ei[N_EDGES + e];
        int pos = atomicAdd(&g_cursor[d], 1);
        if (pos < BSTRIDE) g_bucket[(size_t)d * BSTRIDE + pos] = ei[e];
    }
}

__global__ void k_dinv() {
    int i = blockIdx.x * blockDim.x + threadIdx.x;
    if (i < N_NODES) g_dinv[i] = rsqrtf((float)(g_cursor[i] + 1));  // +1 self loop
}

// ---------------- bf16 tensor-core GEMM (m16n8k16 + cp.async + ldmatrix) ----
__device__ __forceinline__ void mma16(float* d, const uint32_t* a, const uint32_t* b) {
    asm volatile(
        "mma.sync.aligned.m16n8k16.row.col.f32.bf16.bf16.f32 "
        "{%0,%1,%2,%3},{%4,%5,%6,%7},{%8,%9},{%0,%1,%2,%3};"
        : "+f"(d[0]), "+f"(d[1]), "+f"(d[2]), "+f"(d[3])
        : "r"(a[0]), "r"(a[1]), "r"(a[2]), "r"(a[3]), "r"(b[0]), "r"(b[1]));
}

// BM=128, BN=128, BK=32 (16 kpairs), 512 threads = 16 warps (4x4), warp 32x32.
// A: [M][128] uint32 kpairs. BT: [N][128] uint32 kpairs. smem stride 20 uint32.
template<int LAYER>
__global__ __launch_bounds__(512, 2) void gemm_bf() {
    constexpr int N = (LAYER == 0) ? 256 : 128;
    constexpr int M = N_NODES;
    constexpr int KP = 128;
    const uint32_t* A  = (LAYER == 0) ? g_xb : (const uint32_t*)g_a1b;
    const uint32_t* BT = (LAYER == 0) ? g_wt1 : g_wt2;
    uint32_t* C = (LAYER == 0) ? (uint32_t*)g_h1b : (uint32_t*)g_h2b;

    __shared__ uint32_t As[2][128 * 20];
    __shared__ uint32_t Bs[2][128 * 20];

    int tid = threadIdx.x, lane = tid & 31, warp = tid >> 5;
    int wm = warp & 3, wn = warp >> 2;
    int row0 = blockIdx.x * 128, col0 = blockIdx.y * 128;

    int crow = tid >> 2, cch = (tid & 3) * 4;
    bool aok = (row0 + crow) < M;
    uint32_t a_src_sz = aok ? 16u : 0u;
    const uint32_t* aptr = A  + (size_t)(row0 + crow) * KP + cch;
    const uint32_t* bptr = BT + (size_t)(col0 + crow) * KP + cch;

    uint32_t asb = (uint32_t)__cvta_generic_to_shared(&As[0][0]);
    uint32_t bsb = (uint32_t)__cvta_generic_to_shared(&Bs[0][0]);
    uint32_t aw = asb + (crow * 20 + cch) * 4;   // this thread's cp dst in As[0]
    uint32_t bw = bsb + (crow * 20 + cch) * 4;
    constexpr uint32_t BUF = 128 * 20 * 4;

    float acc[2][4][4];
    #pragma unroll
    for (int mt = 0; mt < 2; mt++)
        #pragma unroll
        for (int nt = 0; nt < 4; nt++)
            #pragma unroll
            for (int i = 0; i < 4; i++) acc[mt][nt][i] = 0.0f;

    // ldmatrix source offsets (uint32 units within a buffer)
    int lr = lane & 7;
    int a_m  = wm * 32 + lr + ((lane >> 3) & 1) * 8;   // + mt*16
    int a_kp = ((lane >> 4) & 1) * 4;                  // + kk
    int b_n  = wn * 32 + lr + ((lane >> 4) & 1) * 8;   // + nt0*8
    int b_kp = ((lane >> 3) & 1) * 4;                  // + kk

    auto issue = [&](int t, int buf) {
        cp16(aw + buf * BUF, aptr + t * 16, a_src_sz);
        cp16(bw + buf * BUF, bptr + t * 16, 16u);
        cp_commit();
    };
    auto compute = [&](int buf) {
        uint32_t abase = asb + buf * BUF;
        uint32_t bbase = bsb + buf * BUF;
        #pragma unroll
        for (int kk = 0; kk < 16; kk += 8) {
            uint32_t af[2][4], bf[4][2];
            #pragma unroll
            for (int mt = 0; mt < 2; mt++)
                ldsm4(af[mt], abase + ((a_m + mt * 16) * 20 + a_kp + kk) * 4);
            #pragma unroll
            for (int n0 = 0; n0 < 2; n0++) {
                uint32_t t4[4];
                ldsm4(t4, bbase + ((b_n + n0 * 16) * 20 + b_kp + kk) * 4);
                bf[n0 * 2 + 0][0] = t4[0]; bf[n0 * 2 + 0][1] = t4[1];
                bf[n0 * 2 + 1][0] = t4[2]; bf[n0 * 2 + 1][1] = t4[3];
            }
            #pragma unroll
            for (int mt = 0; mt < 2; mt++)
                #pragma unroll
                for (int nt = 0; nt < 4; nt++)
                    mma16(acc[mt][nt], af[mt], bf[nt]);
        }
    };

    issue(0, 0);
    issue(1, 1);
    #pragma unroll 1
    for (int t = 0; t < 8; t++) {
        if (t < 7) cp_wait<1>(); else cp_wait<0>();
        __syncthreads();
        compute(t & 1);
        __syncthreads();
        if (t + 2 < 8) issue(t + 2, t & 1);
    }

    // epilogue
    int r = lane >> 2, c = lane & 3;
    constexpr int NU = N / 2;
    #pragma unroll
    for (int mt = 0; mt < 2; mt++) {
        int gr = row0 + wm * 32 + mt * 16 + r;
        bool ok0 = gr < M, ok1 = (gr + 8) < M;
        float dv0 = 1.0f, dv1 = 1.0f;
        if (LAYER == 1) {
            dv0 = ok0 ? g_dinv[gr] : 0.0f;
            dv1 = ok1 ? g_dinv[gr + 8] : 0.0f;
        }
        #pragma unroll
        for (int nt = 0; nt < 4; nt++) {
            int gcu = (col0 + wn * 32 + nt * 8) / 2 + c;
            if (ok0)
                C[(size_t)gr * NU + gcu] =
                    f2bf2(acc[mt][nt][0] * dv0, acc[mt][nt][1] * dv0);
            if (ok1)
                C[(size_t)(gr + 8) * NU + gcu] =
                    f2bf2(acc[mt][nt][2] * dv1, acc[mt][nt][3] * dv1);
        }
    }
}

// ---------------- aggregation ----------------
// LAYER 0 (h1 unscaled): out[v] = relu(dv*(dv*h[v] + sum_s dinv[s]*h[s]) + b)
// LAYER 1 (h2 pre-scaled): out[v] = relu(dv*(h[v] + sum_s h[s]) + b) -> pool
template<int LAYER>
__global__ void agg_kernel(const float* __restrict__ bias,
                           const int* __restrict__ batch) {
    constexpr int NA = (LAYER == 0) ? 8 : 4;
    int w    = (blockIdx.x * blockDim.x + threadIdx.x) >> 5;
    int lane = threadIdx.x & 31;
    if (w >= N_NODES) return;
    float dv = g_dinv[w];
    float acc[NA];
    #pragma unroll
    for (int j = 0; j < NA; j++) acc[j] = 0.0f;
    int deg = min(g_cursor[w], BSTRIDE);
    const int* bk = g_bucket + (size_t)w * BSTRIDE;

    if (LAYER == 0) {
        const uint4* h = (const uint4*)g_h1b;
        uint4 u = h[(size_t)w * 32 + lane];
        fmabf2(acc + 0, u.x, dv); fmabf2(acc + 2, u.y, dv);
        fmabf2(acc + 4, u.z, dv); fmabf2(acc + 6, u.w, dv);
        int e = 0;
        for (; e + 4 <= deg; e += 4) {
            int s0 = bk[e], s1 = bk[e + 1], s2 = bk[e + 2], s3 = bk[e + 3];
            float w0 = g_dinv[s0], w1 = g_dinv[s1];
            float w2 = g_dinv[s2], w3 = g_dinv[s3];
            uint4 u0 = h[(size_t)s0 * 32 + lane];
            uint4 u1 = h[(size_t)s1 * 32 + lane];
            uint4 u2 = h[(size_t)s2 * 32 + lane];
            uint4 u3 = h[(size_t)s3 * 32 + lane];
            fmabf2(acc + 0, u0.x, w0); fmabf2(acc + 2, u0.y, w0);
            fmabf2(acc + 4, u0.z, w0); fmabf2(acc + 6, u0.w, w0);
            fmabf2(acc + 0, u1.x, w1); fmabf2(acc + 2, u1.y, w1);
            fmabf2(acc + 4, u1.z, w1); fmabf2(acc + 6, u1.w, w1);
            fmabf2(acc + 0, u2.x, w2); fmabf2(acc + 2, u2.y, w2);
            fmabf2(acc + 4, u2.z, w2); fmabf2(acc + 6, u2.w, w2);
            fmabf2(acc + 0, u3.x, w3); fmabf2(acc + 2, u3.y, w3);
            fmabf2(acc + 4, u3.z, w3); fmabf2(acc + 6, u3.w, w3);
        }
        for (; e < deg; e++) {
            int s = bk[e];
            float ws = g_dinv[s];
            uint4 uu = h[(size_t)s * 32 + lane];
            fmabf2(acc + 0, uu.x, ws); fmabf2(acc + 2, uu.y, ws);
            fmabf2(acc + 4, uu.z, ws); fmabf2(acc + 6, uu.w, ws);
        }
        float o[8];
        #pragma unroll
        for (int j = 0; j < 8; j++)
            o[j] = fmaxf(dv * acc[j] + bias[lane * 8 + j], 0.0f);
        g_a1b[(size_t)w * 32 + lane] =
            make_uint4(f2bf2(o[0], o[1]), f2bf2(o[2], o[3]),
                       f2bf2(o[4], o[5]), f2bf2(o[6], o[7]));
    } else {
        const uint2* h = (const uint2*)g_h2b;
        uint2 u = h[(size_t)w * 32 + lane];
        addbf2(acc + 0, u.x); addbf2(acc + 2, u.y);
        int e = 0;
        for (; e + 4 <= deg; e += 4) {
            int s0 = bk[e], s1 = bk[e + 1], s2 = bk[e + 2], s3 = bk[e + 3];
            uint2 u0 = h[(size_t)s0 * 32 + lane];
            uint2 u1 = h[(size_t)s1 * 32 + lane];
            uint2 u2 = h[(size_t)s2 * 32 + lane];
            uint2 u3 = h[(size_t)s3 * 32 + lane];
            addbf2(acc + 0, u0.x); addbf2(acc + 2, u0.y);
            addbf2(acc + 0, u1.x); addbf2(acc + 2, u1.y);
            addbf2(acc + 0, u2.x); addbf2(acc + 2, u2.y);
            addbf2(acc + 0, u3.x); addbf2(acc + 2, u3.y);
        }
        for (; e < deg; e++) {
            uint2 uu = h[(size_t)bk[e] * 32 + lane];
            addbf2(acc + 0, uu.x); addbf2(acc + 2, uu.y);
        }
        int g = batch[w];
        #pragma unroll
        for (int j = 0; j < 4; j++) {
            float v = fmaxf(dv * acc[j] + bias[lane * 4 + j], 0.0f);
            atomicAdd(&g_pool[g * D2 + lane * 4 + j], v);
        }
        if (lane == 0) atomicAdd(&g_pcnt[g], 1.0f);
    }
}

// ---------------- MLP head ----------------
__global__ void k_head(const float* __restrict__ Wl1, const float* __restrict__ bl1,
                       const float* __restrict__ Wl2, const float* __restrict__ bl2,
                       float* __restrict__ out) {
    __shared__ float gv[128];
    __shared__ float hid[64];
    int g = blockIdx.x, t = threadIdx.x;
    float cgt = fmaxf(g_pcnt[g], 1.0f);
    gv[t] = g_pool[g * D2 + t] / cgt;
    __syncthreads();
    if (t < 64) {
        float s = bl1[t];
        #pragma unroll 4
        for (int k = 0; k < 128; k++) s += gv[k] * Wl1[k * 64 + t];
        hid[t] = fmaxf(s, 0.0f);
    }
    __syncthreads();
    if (t == 0) {
        float s = bl2[0];
        #pragma unroll 4
        for (int k = 0; k < 64; k++) s += hid[k] * Wl2[k];
        out[g] = 1.0f / (1.0f + expf(-s));
    }
}

// ---------------- launch ----------------
extern "C" void kernel_launch(void* const* d_in, const int* in_sizes, int n_in,
                              void* d_out, int out_size) {
    const float* x    = (const float*)d_in[0];
    const int*   ei   = (const int*)d_in[1];
    const int*   bat  = (const int*)d_in[2];
    const float* W1   = (const float*)d_in[3];
    const float* b1   = (const float*)d_in[4];
    const float* W2   = (const float*)d_in[5];
    const float* b2   = (const float*)d_in[6];
    const float* Wl1  = (const float*)d_in[7];
    const float* bl1  = (const float*)d_in[8];
    const float* Wl2  = (const float*)d_in[9];
    const float* bl2  = (const float*)d_in[10];
    float* out = (float*)d_out;

    cudaStream_t s1;
    cudaEvent_t evA, evW, evCsr;
    cudaStreamCreateWithFlags(&s1, cudaStreamNonBlocking);
    cudaEventCreateWithFlags(&evA,   cudaEventDisableTiming);
    cudaEventCreateWithFlags(&evW,   cudaEventDisableTiming);
    cudaEventCreateWithFlags(&evCsr, cudaEventDisableTiming);

    cudaEventRecord(evA, 0);
    cudaStreamWaitEvent(s1, evA, 0);

    // side branch: weight conversion first (gemm1 needs it), then CSR build
    k_cvt_w<<<(256 * 128 + 128 * 128 + 255) / 256, 256, 0, s1>>>(W1, W2);
    cudaEventRecord(evW, s1);
    k_init<<<(N_NODES + 255) / 256, 256, 0, s1>>>();
    k_fill<<<(N_EDGES + 255) / 256, 256, 0, s1>>>(ei);
    k_dinv<<<(N_NODES + 255) / 256, 256, 0, s1>>>();
    cudaEventRecord(evCsr, s1);

    // main branch: convert x (runs concurrently with side branch)
    k_cvt_x<<<(N_NODES * 128 + 255) / 256, 256>>>(x);
    cudaStreamWaitEvent(0, evW, 0);
    {
        dim3 grid((N_NODES + 127) / 128, D1 / 128);
        gemm_bf<0><<<grid, 512>>>();
    }
    cudaStreamWaitEvent(0, evCsr, 0);
    agg_kernel<0><<<(N_NODES * 32 + 255) / 256, 256>>>(b1, nullptr);

    {
        dim3 grid((N_NODES + 127) / 128, D2 / 128);
        gemm_bf<1><<<grid, 512>>>();
    }
    agg_kernel<1><<<(N_NODES * 32 + 255) / 256, 256>>>(b2, bat);

    k_head<<<NUM_G, 128>>>(Wl1, bl1, Wl2, bl2, out);
}

// round 15
// speedup vs baseline: 1.2284x; 1.0020x over previous
#include <cuda_runtime.h>
#include <math.h>
#include <stdint.h>

#define N_NODES  20000
#define N_EDGES  320000
#define NUM_G    64
#define D1       256
#define D2       128
#define BSTRIDE  96      // bucket slots per node; Poisson(16) => P(deg>=96) ~ 0

// ---------------- scratch (device globals) -------------
__device__ float    g_dinv[N_NODES];
__device__ int      g_cursor[N_NODES];            // doubles as degree count
__device__ int      g_bucket[(size_t)N_NODES * BSTRIDE];
__device__ uint32_t g_xb[(size_t)N_NODES * 128];  // bf16x2-packed x
__device__ uint32_t g_wt1[256 * 128];             // bf16x2 W1^T [n][kpair]
__device__ uint32_t g_wt2[128 * 128];             // bf16x2 W2^T [n][kpair]
__device__ uint4    g_h1b[(size_t)N_NODES * (D1 / 8)];  // x@W1 (UNscaled)
__device__ uint4    g_a1b[(size_t)N_NODES * (D1 / 8)];  // relu(...)
__device__ uint2    g_h2b[(size_t)N_NODES * (D2 / 4)];  // dinv*(a1@W2)
__device__ float    g_pool[NUM_G * D2];
__device__ float    g_pcnt[NUM_G];

// ---------------- helpers ----------------
__device__ __forceinline__ uint32_t f2bf2(float lo, float hi) {
    uint32_t r;
    asm("cvt.rn.bf16x2.f32 %0, %1, %2;" : "=r"(r) : "f"(hi), "f"(lo));
    return r;
}
__device__ __forceinline__ void addbf2(float* a, uint32_t u) {
    a[0] += __uint_as_float(u << 16);
    a[1] += __uint_as_float(u & 0xffff0000u);
}
__device__ __forceinline__ void fmabf2(float* a, uint32_t u, float w) {
    a[0] = fmaf(w, __uint_as_float(u << 16), a[0]);
    a[1] = fmaf(w, __uint_as_float(u & 0xffff0000u), a[1]);
}
__device__ __forceinline__ void cp16(uint32_t dst, const void* src, uint32_t srcsize) {
    asm volatile("cp.async.cg.shared.global [%0], [%1], 16, %2;"
                 :: "r"(dst), "l"(src), "r"(srcsize));
}
__device__ __forceinline__ void cp_commit() {
    asm volatile("cp.async.commit_group;");
}
template<int N>
__device__ __forceinline__ void cp_wait() {
    asm volatile("cp.async.wait_group %0;" :: "n"(N));
}
__device__ __forceinline__ void ldsm4(uint32_t* r, uint32_t addr) {
    asm volatile("ldmatrix.sync.aligned.m8n8.x4.shared.b16 {%0,%1,%2,%3}, [%4];"
                 : "=r"(r[0]), "=r"(r[1]), "=r"(r[2]), "=r"(r[3]) : "r"(addr));
}

// ---------------- init ----------------
__global__ void k_init() {
    int i = blockIdx.x * blockDim.x + threadIdx.x;
    if (i < N_NODES) g_cursor[i] = 0;
    if (i < NUM_G * D2) g_pool[i] = 0.0f;
    if (i < NUM_G) g_pcnt[i] = 0.0f;
}

// ---------------- conversions ----------------
__global__ void k_cvt_x(const float* __restrict__ x) {
    int i = blockIdx.x * blockDim.x + threadIdx.x;
    if (i < N_NODES * 128) {
        float2 v = ((const float2*)x)[i];
        g_xb[i] = f2bf2(v.x, v.y);
    }
}
// W [K][N] fp32 row-major -> WT [n][kpair] bf16x2
__global__ void k_cvt_w(const float* __restrict__ W1, const float* __restrict__ W2) {
    int i = blockIdx.x * blockDim.x + threadIdx.x;
    if (i < 256 * 128) {
        int n = i & 255, kp = i >> 8;
        g_wt1[(size_t)n * 128 + kp] = f2bf2(W1[(2 * kp) * 256 + n],
                                            W1[(2 * kp + 1) * 256 + n]);
    } else if (i < 256 * 128 + 128 * 128) {
        int j = i - 256 * 128;
        int n = j & 127, kp = j >> 7;
        g_wt2[(size_t)n * 128 + kp] = f2bf2(W2[(2 * kp) * 128 + n],
                                            W2[(2 * kp + 1) * 128 + n]);
    }
}

// ---------------- bucket fill (cursor ends up = degree) ----------------
__global__ void k_fill(const int* __restrict__ ei) {
    int e = blockIdx.x * blockDim.x + threadIdx.x;
    if (e < N_EDGES) {
        int d = ei[N_EDGES + e];
        int pos = atomicAdd(&g_cursor[d], 1);
        if (pos < BSTRIDE) g_bucket[(size_t)d * BSTRIDE + pos] = ei[e];
    }
}

__global__ void k_dinv() {
    int i = blockIdx.x * blockDim.x + threadIdx.x;
    if (i < N_NODES) g_dinv[i] = rsqrtf((float)(g_cursor[i] + 1));  // +1 self loop
}

// ---------------- bf16 tensor-core GEMM (4-stage cp.async, 1 barrier/tile) --
__device__ __forceinline__ void mma16(float* d, const uint32_t* a, const uint32_t* b) {
    asm volatile(
        "mma.sync.aligned.m16n8k16.row.col.f32.bf16.bf16.f32 "
        "{%0,%1,%2,%3},{%4,%5,%6,%7},{%8,%9},{%0,%1,%2,%3};"
        : "+f"(d[0]), "+f"(d[1]), "+f"(d[2]), "+f"(d[3])
        : "r"(a[0]), "r"(a[1]), "r"(a[2]), "r"(a[3]), "r"(b[0]), "r"(b[1]));
}

// BM=128, BN=128, BK=32 (16 kpairs), 512 threads = 16 warps (4x4), warp 32x32.
// A: [M][128] uint32 kpairs. BT: [N][128] uint32 kpairs. smem stride 20 uint32.
// 4-stage ring in dynamic smem; single __syncthreads per k-tile.
#define GEMM_STAGES 4
#define TILE_U32   (128 * 20)                      // per array per stage
template<int LAYER>
__global__ __launch_bounds__(512, 2) void gemm_bf() {
    constexpr int N = (LAYER == 0) ? 256 : 128;
    constexpr int M = N_NODES;
    constexpr int KP = 128;
    constexpr int NT = 8;                          // k-tiles (8 * 16 kpairs = 128)
    const uint32_t* A  = (LAYER == 0) ? g_xb : (const uint32_t*)g_a1b;
    const uint32_t* BT = (LAYER == 0) ? g_wt1 : g_wt2;
    uint32_t* C = (LAYER == 0) ? (uint32_t*)g_h1b : (uint32_t*)g_h2b;

    extern __shared__ uint32_t smem[];
    uint32_t* Asm = smem;                           // [GEMM_STAGES][TILE_U32]
    uint32_t* Bsm = smem + GEMM_STAGES * TILE_U32;  // [GEMM_STAGES][TILE_U32]

    int tid = threadIdx.x, lane = tid & 31, warp = tid >> 5;
    int wm = warp & 3, wn = warp >> 2;
    int row0 = blockIdx.x * 128, col0 = blockIdx.y * 128;

    int crow = tid >> 2, cch = (tid & 3) * 4;
    bool aok = (row0 + crow) < M;
    uint32_t a_src_sz = aok ? 16u : 0u;
    const uint32_t* aptr = A  + (size_t)(row0 + crow) * KP + cch;
    const uint32_t* bptr = BT + (size_t)(col0 + crow) * KP + cch;

    uint32_t asb = (uint32_t)__cvta_generic_to_shared(Asm);
    uint32_t bsb = (uint32_t)__cvta_generic_to_shared(Bsm);
    uint32_t aw = asb + (crow * 20 + cch) * 4;
    uint32_t bw = bsb + (crow * 20 + cch) * 4;
    constexpr uint32_t BUFB = TILE_U32 * 4;         // bytes per stage

    float acc[2][4][4];
    #pragma unroll
    for (int mt = 0; mt < 2; mt++)
        #pragma unroll
        for (int nt = 0; nt < 4; nt++)
            #pragma unroll
            for (int i = 0; i < 4; i++) acc[mt][nt][i] = 0.0f;

    int lr = lane & 7;
    int a_m  = wm * 32 + lr + ((lane >> 3) & 1) * 8;
    int a_kp = ((lane >> 4) & 1) * 4;
    int b_n  = wn * 32 + lr + ((lane >> 4) & 1) * 8;
    int b_kp = ((lane >> 3) & 1) * 4;

    auto issue = [&](int t) {
        int buf = t & (GEMM_STAGES - 1);
        cp16(aw + buf * BUFB, aptr + t * 16, a_src_sz);
        cp16(bw + buf * BUFB, bptr + t * 16, 16u);
        cp_commit();
    };
    auto compute = [&](int t) {
        int buf = t & (GEMM_STAGES - 1);
        uint32_t abase = asb + buf * BUFB;
        uint32_t bbase = bsb + buf * BUFB;
        #pragma unroll
        for (int kk = 0; kk < 16; kk += 8) {
            uint32_t af[2][4], bf[4][2];
            #pragma unroll
            for (int mt = 0; mt < 2; mt++)
                ldsm4(af[mt], abase + ((a_m + mt * 16) * 20 + a_kp + kk) * 4);
            #pragma unroll
            for (int n0 = 0; n0 < 2; n0++) {
                uint32_t t4[4];
                ldsm4(t4, bbase + ((b_n + n0 * 16) * 20 + b_kp + kk) * 4);
                bf[n0 * 2 + 0][0] = t4[0]; bf[n0 * 2 + 0][1] = t4[1];
                bf[n0 * 2 + 1][0] = t4[2]; bf[n0 * 2 + 1][1] = t4[3];
            }
            #pragma unroll
            for (int mt = 0; mt < 2; mt++)
                #pragma unroll
                for (int nt = 0; nt < 4; nt++)
                    mma16(acc[mt][nt], af[mt], bf[nt]);
        }
    };

    issue(0); issue(1); issue(2);                  // 3-deep prologue
    #pragma unroll 1
    for (int t = 0; t < NT; t++) {
        if (t + 3 < NT) cp_wait<2>(); else if (t + 2 < NT) cp_wait<1>(); else cp_wait<0>();
        __syncthreads();                           // single barrier per tile
        compute(t);
        if (t + 3 < NT) issue(t + 3);              // stage (t+3)%4 == (t-1)%4: consumed
    }

    // epilogue
    int r = lane >> 2, c = lane & 3;
    constexpr int NU = N / 2;
    #pragma unroll
    for (int mt = 0; mt < 2; mt++) {
        int gr = row0 + wm * 32 + mt * 16 + r;
        bool ok0 = gr < M, ok1 = (gr + 8) < M;
        float dv0 = 1.0f, dv1 = 1.0f;
        if (LAYER == 1) {
            dv0 = ok0 ? g_dinv[gr] : 0.0f;
            dv1 = ok1 ? g_dinv[gr + 8] : 0.0f;
        }
        #pragma unroll
        for (int nt = 0; nt < 4; nt++) {
            int gcu = (col0 + wn * 32 + nt * 8) / 2 + c;
            if (ok0)
                C[(size_t)gr * NU + gcu] =
                    f2bf2(acc[mt][nt][0] * dv0, acc[mt][nt][1] * dv0);
            if (ok1)
                C[(size_t)(gr + 8) * NU + gcu] =
                    f2bf2(acc[mt][nt][2] * dv1, acc[mt][nt][3] * dv1);
        }
    }
}
#define GEMM_SMEM_BYTES (2 * GEMM_STAGES * TILE_U32 * 4)

// ---------------- aggregation ----------------
// LAYER 0 (h1 unscaled): out[v] = relu(dv*(dv*h[v] + sum_s dinv[s]*h[s]) + b)
// LAYER 1 (h2 pre-scaled): out[v] = relu(dv*(h[v] + sum_s h[s]) + b) -> pool
template<int LAYER>
__global__ void agg_kernel(const float* __restrict__ bias,
                           const int* __restrict__ batch) {
    constexpr int NA = (LAYER == 0) ? 8 : 4;
    int w    = (blockIdx.x * blockDim.x + threadIdx.x) >> 5;
    int lane = threadIdx.x & 31;
    if (w >= N_NODES) return;
    float dv = g_dinv[w];
    float acc[NA];
    #pragma unroll
    for (int j = 0; j < NA; j++) acc[j] = 0.0f;
    int deg = min(g_cursor[w], BSTRIDE);
    const int* bk = g_bucket + (size_t)w * BSTRIDE;

    if (LAYER == 0) {
        const uint4* h = (const uint4*)g_h1b;
        uint4 u = h[(size_t)w * 32 + lane];
        fmabf2(acc + 0, u.x, dv); fmabf2(acc + 2, u.y, dv);
        fmabf2(acc + 4, u.z, dv); fmabf2(acc + 6, u.w, dv);
        int e = 0;
        for (; e + 4 <= deg; e += 4) {
            int s0 = bk[e], s1 = bk[e + 1], s2 = bk[e + 2], s3 = bk[e + 3];
            float w0 = g_dinv[s0], w1 = g_dinv[s1];
            float w2 = g_dinv[s2], w3 = g_dinv[s3];
            uint4 u0 = h[(size_t)s0 * 32 + lane];
            uint4 u1 = h[(size_t)s1 * 32 + lane];
            uint4 u2 = h[(size_t)s2 * 32 + lane];
            uint4 u3 = h[(size_t)s3 * 32 + lane];
            fmabf2(acc + 0, u0.x, w0); fmabf2(acc + 2, u0.y, w0);
            fmabf2(acc + 4, u0.z, w0); fmabf2(acc + 6, u0.w, w0);
            fmabf2(acc + 0, u1.x, w1); fmabf2(acc + 2, u1.y, w1);
            fmabf2(acc + 4, u1.z, w1); fmabf2(acc + 6, u1.w, w1);
            fmabf2(acc + 0, u2.x, w2); fmabf2(acc + 2, u2.y, w2);
            fmabf2(acc + 4, u2.z, w2); fmabf2(acc + 6, u2.w, w2);
            fmabf2(acc + 0, u3.x, w3); fmabf2(acc + 2, u3.y, w3);
            fmabf2(acc + 4, u3.z, w3); fmabf2(acc + 6, u3.w, w3);
        }
        for (; e < deg; e++) {
            int s = bk[e];
            float ws = g_dinv[s];
            uint4 uu = h[(size_t)s * 32 + lane];
            fmabf2(acc + 0, uu.x, ws); fmabf2(acc + 2, uu.y, ws);
            fmabf2(acc + 4, uu.z, ws); fmabf2(acc + 6, uu.w, ws);
        }
        float o[8];
        #pragma unroll
        for (int j = 0; j < 8; j++)
            o[j] = fmaxf(dv * acc[j] + bias[lane * 8 + j], 0.0f);
        g_a1b[(size_t)w * 32 + lane] =
            make_uint4(f2bf2(o[0], o[1]), f2bf2(o[2], o[3]),
                       f2bf2(o[4], o[5]), f2bf2(o[6], o[7]));
    } else {
        const uint2* h = (const uint2*)g_h2b;
        uint2 u = h[(size_t)w * 32 + lane];
        addbf2(acc + 0, u.x); addbf2(acc + 2, u.y);
        int e = 0;
        for (; e + 4 <= deg; e += 4) {
            int s0 = bk[e], s1 = bk[e + 1], s2 = bk[e + 2], s3 = bk[e + 3];
            uint2 u0 = h[(size_t)s0 * 32 + lane];
            uint2 u1 = h[(size_t)s1 * 32 + lane];
            uint2 u2 = h[(size_t)s2 * 32 + lane];
            uint2 u3 = h[(size_t)s3 * 32 + lane];
            addbf2(acc + 0, u0.x); addbf2(acc + 2, u0.y);
            addbf2(acc + 0, u1.x); addbf2(acc + 2, u1.y);
            addbf2(acc + 0, u2.x); addbf2(acc + 2, u2.y);
            addbf2(acc + 0, u3.x); addbf2(acc + 2, u3.y);
        }
        for (; e < deg; e++) {
            uint2 uu = h[(size_t)bk[e] * 32 + lane];
            addbf2(acc + 0, uu.x); addbf2(acc + 2, uu.y);
        }
        int g = batch[w];
        #pragma unroll
        for (int j = 0; j < 4; j++) {
            float v = fmaxf(dv * acc[j] + bias[lane * 4 + j], 0.0f);
            atomicAdd(&g_pool[g * D2 + lane * 4 + j], v);
        }
        if (lane == 0) atomicAdd(&g_pcnt[g], 1.0f);
    }
}

// ---------------- MLP head ----------------
__global__ void k_head(const float* __restrict__ Wl1, const float* __restrict__ bl1,
                       const float* __restrict__ Wl2, const float* __restrict__ bl2,
                       float* __restrict__ out) {
    __shared__ float gv[128];
    __shared__ float hid[64];
    int g = blockIdx.x, t = threadIdx.x;
    float cgt = fmaxf(g_pcnt[g], 1.0f);
    gv[t] = g_pool[g * D2 + t] / cgt;
    __syncthreads();
    if (t < 64) {
        float s = bl1[t];
        #pragma unroll 4
        for (int k = 0; k < 128; k++) s += gv[k] * Wl1[k * 64 + t];
        hid[t] = fmaxf(s, 0.0f);
    }
    __syncthreads();
    if (t == 0) {
        float s = bl2[0];
        #pragma unroll 4
        for (int k = 0; k < 64; k++) s += hid[k] * Wl2[k];
        out[g] = 1.0f / (1.0f + expf(-s));
    }
}

// ---------------- launch ----------------
extern "C" void kernel_launch(void* const* d_in, const int* in_sizes, int n_in,
                              void* d_out, int out_size) {
    const float* x    = (const float*)d_in[0];
    const int*   ei   = (const int*)d_in[1];
    const int*   bat  = (const int*)d_in[2];
    const float* W1   = (const float*)d_in[3];
    const float* b1   = (const float*)d_in[4];
    const float* W2   = (const float*)d_in[5];
    const float* b2   = (const float*)d_in[6];
    const float* Wl1  = (const float*)d_in[7];
    const float* bl1  = (const float*)d_in[8];
    const float* Wl2  = (const float*)d_in[9];
    const float* bl2  = (const float*)d_in[10];
    float* out = (float*)d_out;

    static bool attr_done = false;
    if (!attr_done) {
        cudaFuncSetAttribute(gemm_bf<0>, cudaFuncAttributeMaxDynamicSharedMemorySize,
                             GEMM_SMEM_BYTES);
        cudaFuncSetAttribute(gemm_bf<1>, cudaFuncAttributeMaxDynamicSharedMemorySize,
                             GEMM_SMEM_BYTES);
        attr_done = true;
    }

    cudaStream_t s1;
    cudaEvent_t evA, evW, evCsr;
    cudaStreamCreateWithFlags(&s1, cudaStreamNonBlocking);
    cudaEventCreateWithFlags(&evA,   cudaEventDisableTiming);
    cudaEventCreateWithFlags(&evW,   cudaEventDisableTiming);
    cudaEventCreateWithFlags(&evCsr, cudaEventDisableTiming);

    cudaEventRecord(evA, 0);
    cudaStreamWaitEvent(s1, evA, 0);

    // side branch: weight conversion first (gemm1 needs it), then CSR build
    k_cvt_w<<<(256 * 128 + 128 * 128 + 255) / 256, 256, 0, s1>>>(W1, W2);
    cudaEventRecord(evW, s1);
    k_init<<<(N_NODES + 255) / 256, 256, 0, s1>>>();
    k_fill<<<(N_EDGES + 255) / 256, 256, 0, s1>>>(ei);
    k_dinv<<<(N_NODES + 255) / 256, 256, 0, s1>>>();
    cudaEventRecord(evCsr, s1);

    // main branch: convert x (runs concurrently with side branch)
    k_cvt_x<<<(N_NODES * 128 + 255) / 256, 256>>>(x);
    cudaStreamWaitEvent(0, evW, 0);
    {
        dim3 grid((N_NODES + 127) / 128, D1 / 128);
        gemm_bf<0><<<grid, 512, GEMM_SMEM_BYTES>>>();
    }
    cudaStreamWaitEvent(0, evCsr, 0);
    agg_kernel<0><<<(N_NODES * 32 + 255) / 256, 256>>>(b1, nullptr);

    {
        dim3 grid((N_NODES + 127) / 128, D2 / 128);
        gemm_bf<1><<<grid, 512, GEMM_SMEM_BYTES>>>();
    }
    agg_kernel<1><<<(N_NODES * 32 + 255) / 256, 256>>>(b2, bat);

    k_head<<<NUM_G, 128>>>(Wl1, bl1, Wl2, bl2, out);
}